// round 11
// baseline (speedup 1.0000x reference)
#include <cuda_runtime.h>
#include <cuda_fp16.h>
#include <mma.h>
#include <math.h>
using namespace nvcuda;

#define Nn   50000
#define Ee   800000
#define EPt  850000   // E + N self loops
#define Gg   64
#define NBLK 49       // ceil(Nn/1024)

// ---------------- scratch ----------------
__device__ __align__(16) __half g_h1  [(size_t)Nn*128];   // fp16 features L1
__device__ __align__(16) __half g_out1[(size_t)Nn*128];   // fp16 layer-1 output
__device__ __align__(16) __half g_h2  [(size_t)Nn*64];    // fp16 features L2
__device__ __align__(16) float  g_asrc1[Nn*4];
__device__ __align__(16) float  g_adst1[Nn*4];
__device__ __align__(16) float  g_asrc2[Nn];
__device__ __align__(16) float  g_adst2[Nn];
__device__ __align__(16) float  g_tae1 [(size_t)Ee*4];
__device__ __align__(16) float  g_tae2 [Ee];
__device__ __align__(16) uint4  g_edge [EPt];   // packed: src | ae1[0:2] | ae1[2:4] | ae2,pad
__device__ __align__(16) int    g_deg  [Nn];
__device__ __align__(16) int    g_off  [Nn+1];
__device__ __align__(16) int    g_cur  [Nn];
__device__ __align__(16) int    g_sflag  [NBLK+1];
__device__ __align__(16) int    g_sprefix[NBLK+1];
__device__ __align__(16) float  g_sum_ea[16];
__device__ __align__(16) float  g_v1[64];
__device__ __align__(16) float  g_v2[16];
__device__ __align__(16) float  g_pool[Gg*64];
__device__ __align__(16) int    g_cnt [Gg];

__device__ __forceinline__ float lrelu(float x){ return x > 0.f ? x : 0.2f*x; }

__device__ __forceinline__ unsigned packh2(float a, float b){
    __half2 h = __float22half2_rn(make_float2(a,b));
    return *(unsigned*)&h;
}
__device__ __forceinline__ uint2 pack4(float4 v){
    uint2 r; r.x = packh2(v.x,v.y); r.y = packh2(v.z,v.w); return r;
}

// ---------------- 1. init: zero scratch + v1/v2 ----------------
__global__ void k_init(const float* __restrict__ We1, const float* __restrict__ ae1,
                       const float* __restrict__ We2, const float* __restrict__ ae2){
    int i = blockIdx.x*blockDim.x + threadIdx.x;
    if(i < Nn){ g_deg[i]=0; g_cur[i]=0; }
    if(i < 16) g_sum_ea[i]=0.f;
    if(i < Gg*64) g_pool[i]=0.f;
    if(i < Gg) g_cnt[i]=0;
    if(i <= NBLK){ g_sflag[i]=0; g_sprefix[i]=0; }
    if(blockIdx.x == 0){
        int t = threadIdx.x;
        if(t < 64){
            int h = t >> 4, d = t & 15;
            float s = 0.f;
            for(int c=0;c<32;c++) s += We1[d*128 + h*32 + c] * ae1[h*32 + c];
            g_v1[h*16 + d] = s;
        }
        if(t < 16){
            float s = 0.f;
            for(int c=0;c<64;c++) s += We2[t*64 + c] * ae2[c];
            g_v2[t] = s;
        }
    }
}

// ---------------- 2. pass1: one thread/edge; hist + a_edge dots + sum_ea ----------------
__global__ __launch_bounds__(256) void k_pass1(const float* __restrict__ ea,
                                               const int* __restrict__ ei){
    __shared__ float sv1[64], sv2[16], ssum[16];
    int t = threadIdx.x;
    if(t < 64) sv1[t] = g_v1[t];
    if(t < 16){ sv2[t] = g_v2[t]; ssum[t] = 0.f; }
    __syncthreads();
    int e = blockIdx.x*blockDim.x + t;
    float r[16];
#pragma unroll
    for(int i=0;i<16;i++) r[i]=0.f;
    if(e < EPt){
        int d = (e < Ee) ? __ldg(&ei[Ee + e]) : (e - Ee);
        atomicAdd(&g_deg[d], 1);
    }
    if(e < Ee){
        const float4* rp = (const float4*)(ea + (size_t)e*16);
        ((float4*)r)[0]=__ldg(rp);   ((float4*)r)[1]=__ldg(rp+1);
        ((float4*)r)[2]=__ldg(rp+2); ((float4*)r)[3]=__ldg(rp+3);
        float ae[4];
#pragma unroll
        for(int h=0;h<4;h++){
            float a=0.f;
#pragma unroll
            for(int i=0;i<16;i++) a += sv1[h*16+i]*r[i];
            ae[h]=a;
        }
        float a2=0.f;
#pragma unroll
        for(int i=0;i<16;i++) a2 += sv2[i]*r[i];
        *(float4*)&g_tae1[(size_t)e*4] = make_float4(ae[0],ae[1],ae[2],ae[3]);
        g_tae2[e] = a2;
    }
#pragma unroll
    for(int off=16; off; off>>=1)
#pragma unroll
        for(int i=0;i<16;i++) r[i] += __shfl_xor_sync(0xffffffffu, r[i], off);
    if((t & 31)==0)
#pragma unroll
        for(int i=0;i<16;i++) atomicAdd(&ssum[i], r[i]);
    __syncthreads();
    if(t < 16) atomicAdd(&g_sum_ea[t], ssum[t]);
}

// ---------------- 3. single-kernel chained scan (49 blocks, all resident) ----------------
__global__ __launch_bounds__(256) void k_scan(){
    __shared__ int wsum[8], wexc[8];
    __shared__ int s_prefix;
    int t = threadIdx.x, blk = blockIdx.x;
    int base = blk*1024 + t*4;
    int v0 = (base+0<Nn)?g_deg[base+0]:0;
    int v1 = (base+1<Nn)?g_deg[base+1]:0;
    int v2 = (base+2<Nn)?g_deg[base+2]:0;
    int v3 = (base+3<Nn)?g_deg[base+3]:0;
    int s = v0+v1+v2+v3;
    int lane = t&31, w = t>>5;
    int ps = s;
#pragma unroll
    for(int off=1; off<32; off<<=1){
        int n = __shfl_up_sync(0xffffffffu, ps, off);
        if(lane>=off) ps += n;
    }
    if(lane==31) wsum[w] = ps;
    __syncthreads();
    if(t==0){
        int r=0;
#pragma unroll
        for(int k=0;k<8;k++){ wexc[k]=r; r+=wsum[k]; }
        int prefix = 0;
        if(blk > 0){
            while(atomicAdd(&g_sflag[blk], 0) == 0){}
            __threadfence();
            prefix = g_sprefix[blk];
        }
        g_sprefix[blk+1] = prefix + r;
        __threadfence();
        atomicExch(&g_sflag[blk+1], 1);
        s_prefix = prefix;
    }
    __syncthreads();
    int run = s_prefix + wexc[w] + ps - s;
    if(base+0<Nn) g_off[base+0]=run; run+=v0;
    if(base+1<Nn) g_off[base+1]=run; run+=v1;
    if(base+2<Nn) g_off[base+2]=run; run+=v2;
    if(base+3<Nn) g_off[base+3]=run;
    if(blk==NBLK-1 && t==255) g_off[Nn]=EPt;
}

// ---------------- 4. scatter: packed 16-B edge records; inline self-loop lae ----------------
__global__ __launch_bounds__(256) void k_scatter(const int* __restrict__ ei){
    __shared__ float sv1[64], sv2[16], smean[16];
    int t = threadIdx.x;
    if(t < 64) sv1[t] = g_v1[t];
    if(t < 16){ sv2[t] = g_v2[t]; smean[t] = g_sum_ea[t] * (1.0f/(float)Ee); }
    __syncthreads();
    int e = blockIdx.x*blockDim.x + t;
    if(e >= EPt) return;
    int s, d; uint4 rec;
    if(e < Ee){
        s = __ldg(&ei[e]); d = __ldg(&ei[Ee + e]);
        float4 ae = *(const float4*)&g_tae1[(size_t)e*4];
        float ae2 = g_tae2[e];
        uint2 p = pack4(ae);
        rec.x = (unsigned)s; rec.y = p.x; rec.z = p.y; rec.w = packh2(ae2, 0.f);
    } else {
        s = d = e - Ee;
        float ae[4];
#pragma unroll
        for(int h=0;h<4;h++){
            float a=0.f;
#pragma unroll
            for(int i=0;i<16;i++) a += smean[i]*sv1[h*16+i];
            ae[h]=a;
        }
        float a2=0.f;
#pragma unroll
        for(int i=0;i<16;i++) a2 += smean[i]*sv2[i];
        rec.x = (unsigned)s;
        rec.y = packh2(ae[0],ae[1]); rec.z = packh2(ae[2],ae[3]);
        rec.w = packh2(a2, 0.f);
    }
    int pos = g_off[d] + atomicAdd(&g_cur[d], 1);
    g_edge[pos] = rec;
}

// ---------------- 5. FFMA SGEMM (GEMM1): fp32 A, fp16 C, fused epilogue ----------------
__global__ __launch_bounds__(256) void k_gemm1(const float* __restrict__ A,
                                               const float* __restrict__ W,
                                               const float* __restrict__ atts,
                                               const float* __restrict__ attd,
                                               __half* __restrict__ C,
                                               float* __restrict__ oasrc,
                                               float* __restrict__ oadst, int M){
    constexpr int NC = 128, CPT = 8;
    __shared__ float As[64*36];
    __shared__ float Ws[32*NC];
    __shared__ float as_s[NC], ad_s[NC];
    const int t  = threadIdx.x;
    const int rg = t >> 4, cg = t & 15;
    const int r0 = blockIdx.x * 64;
    if(t < NC){ as_s[t]=__ldg(&atts[t]); ad_s[t]=__ldg(&attd[t]); }
    float acc[4][CPT];
#pragma unroll
    for(int i=0;i<4;i++)
#pragma unroll
        for(int j=0;j<CPT;j++) acc[i][j]=0.f;

    for(int kc=0; kc<128; kc+=32){
#pragma unroll
        for(int i=0;i<2;i++){
            int f = t + i*256; int r = f>>3; int c4 = f&7;
            float4 v = make_float4(0.f,0.f,0.f,0.f);
            if(r0 + r < M) v = __ldg((const float4*)&A[(size_t)(r0+r)*128 + kc + c4*4]);
            float* dst = &As[r*36 + c4*4];
            dst[0]=v.x; dst[1]=v.y; dst[2]=v.z; dst[3]=v.w;
        }
#pragma unroll
        for(int f=t; f < 32*NC/4; f += 256){
            int k = f/(NC/4); int c = f%(NC/4);
            *(float4*)&Ws[k*NC + c*4] = __ldg((const float4*)&W[(size_t)(kc+k)*NC + c*4]);
        }
        __syncthreads();
#pragma unroll 4
        for(int kk=0; kk<32; kk++){
            float a0 = As[(rg*4+0)*36+kk];
            float a1 = As[(rg*4+1)*36+kk];
            float a2 = As[(rg*4+2)*36+kk];
            float a3 = As[(rg*4+3)*36+kk];
            float4 b0 = *(const float4*)&Ws[kk*NC + cg*CPT];
            float4 b1 = *(const float4*)&Ws[kk*NC + cg*CPT + 4];
            acc[0][0]+=a0*b0.x; acc[0][1]+=a0*b0.y; acc[0][2]+=a0*b0.z; acc[0][3]+=a0*b0.w;
            acc[1][0]+=a1*b0.x; acc[1][1]+=a1*b0.y; acc[1][2]+=a1*b0.z; acc[1][3]+=a1*b0.w;
            acc[2][0]+=a2*b0.x; acc[2][1]+=a2*b0.y; acc[2][2]+=a2*b0.z; acc[2][3]+=a2*b0.w;
            acc[3][0]+=a3*b0.x; acc[3][1]+=a3*b0.y; acc[3][2]+=a3*b0.z; acc[3][3]+=a3*b0.w;
            acc[0][4]+=a0*b1.x; acc[0][5]+=a0*b1.y; acc[0][6]+=a0*b1.z; acc[0][7]+=a0*b1.w;
            acc[1][4]+=a1*b1.x; acc[1][5]+=a1*b1.y; acc[1][6]+=a1*b1.z; acc[1][7]+=a1*b1.w;
            acc[2][4]+=a2*b1.x; acc[2][5]+=a2*b1.y; acc[2][6]+=a2*b1.z; acc[2][7]+=a2*b1.w;
            acc[3][4]+=a3*b1.x; acc[3][5]+=a3*b1.y; acc[3][6]+=a3*b1.z; acc[3][7]+=a3*b1.w;
        }
        __syncthreads();
    }
#pragma unroll
    for(int i=0;i<4;i++){
        int row = r0 + rg*4 + i;
        float ps=0.f, pd=0.f;
#pragma unroll
        for(int j=0;j<CPT;j++){
            float a = acc[i][j];
            ps += a*as_s[cg*CPT+j]; pd += a*ad_s[cg*CPT+j];
        }
        ps += __shfl_xor_sync(0xffffffffu, ps, 1); pd += __shfl_xor_sync(0xffffffffu, pd, 1);
        ps += __shfl_xor_sync(0xffffffffu, ps, 2); pd += __shfl_xor_sync(0xffffffffu, pd, 2);
        if((cg&3)==0 && row<M){ oasrc[row*4+(cg>>2)]=ps; oadst[row*4+(cg>>2)]=pd; }
        if(row < M){
            __half2 hh[4];
#pragma unroll
            for(int j=0;j<4;j++)
                hh[j] = __float22half2_rn(make_float2(acc[i][2*j], acc[i][2*j+1]));
            *(uint4*)&C[(size_t)row*NC + cg*CPT] = *(uint4*)hh;
        }
    }
}

// ---------------- 6. wmma GEMM2 (fp16 A + bias + elu, NC=64, fused epilogue) ----------------
__global__ __launch_bounds__(256) void k_gemm2(const __half* __restrict__ A,
                                               const float* __restrict__ W,
                                               const float* __restrict__ abias,
                                               const float* __restrict__ atts,
                                               const float* __restrict__ attd,
                                               __half* __restrict__ C,
                                               float* __restrict__ oasrc,
                                               float* __restrict__ oadst, int M){
    constexpr int NC = 64;
    __shared__ __align__(16) char smem[8192 + 128*NC*2];
    __half* As = (__half*)smem;              // 128x16 (4KB)
    __half* Bs = (__half*)(smem + 4096);     // 16xNC (2KB)
    __half* Cs = (__half*)(smem + 8192);     // 128xNC strip (16KB)
    const int t = threadIdx.x, w = t>>5, lane = t&31;
    const int r0 = blockIdx.x*128;

    wmma::fragment<wmma::accumulator,16,16,16,float> acc[NC/16];
#pragma unroll
    for(int n=0;n<NC/16;n++) wmma::fill_fragment(acc[n], 0.f);

    for(int kc=0; kc<128; kc+=16){
        // stage A: 128x16 fp16 + bias + elu
        {
            int row = t>>1, col = (t&1)*8;
            float f[8] = {0,0,0,0,0,0,0,0};
            if(r0+row < M){
                uint4 u = __ldg((const uint4*)&A[(size_t)(r0+row)*128 + kc + col]);
                float2 a0=__half22float2(*(__half2*)&u.x), a1=__half22float2(*(__half2*)&u.y);
                float2 a2=__half22float2(*(__half2*)&u.z), a3=__half22float2(*(__half2*)&u.w);
                f[0]=a0.x; f[1]=a0.y; f[2]=a1.x; f[3]=a1.y;
                f[4]=a2.x; f[5]=a2.y; f[6]=a3.x; f[7]=a3.y;
                float4 b0 = __ldg((const float4*)&abias[kc+col]);
                float4 b1 = __ldg((const float4*)&abias[kc+col+4]);
                f[0]+=b0.x; f[1]+=b0.y; f[2]+=b0.z; f[3]+=b0.w;
                f[4]+=b1.x; f[5]+=b1.y; f[6]+=b1.z; f[7]+=b1.w;
#pragma unroll
                for(int j=0;j<8;j++) f[j] = f[j]>0.f ? f[j] : expm1f(f[j]);
            }
            __half2 hh[4];
#pragma unroll
            for(int j=0;j<4;j++) hh[j] = __float22half2_rn(make_float2(f[2*j],f[2*j+1]));
            *(uint4*)&As[row*16 + col] = *(uint4*)hh;
        }
        // stage B: 16xNC
        {
            int row = t>>4, col = (t&15)*4;
            float4 v0 = __ldg((const float4*)&W[(size_t)(kc+row)*NC + col]);
            uint2 p = pack4(v0);
            *(uint2*)&Bs[row*NC + col] = p;
        }
        __syncthreads();
        wmma::fragment<wmma::matrix_a,16,16,16,__half,wmma::row_major> af;
        wmma::load_matrix_sync(af, As + w*16*16, 16);
#pragma unroll
        for(int n=0;n<NC/16;n++){
            wmma::fragment<wmma::matrix_b,16,16,16,__half,wmma::row_major> bf;
            wmma::load_matrix_sync(bf, Bs + n*16, NC);
            wmma::mma_sync(acc[n], af, bf, acc[n]);
        }
        __syncthreads();
    }
    // epilogue: f32 scratch -> fp16 strip
    float* fs = (float*)smem + w*256;
#pragma unroll
    for(int n=0;n<NC/16;n++){
        wmma::store_matrix_sync(fs, acc[n], 16, wmma::mem_row_major);
        __syncwarp();
        int r = lane>>1, c = (lane&1)*8;
        float4 u0 = *(float4*)&fs[r*16 + c];
        float4 u1 = *(float4*)&fs[r*16 + c + 4];
        uint2 p0 = pack4(u0), p1 = pack4(u1);
        uint4 packed; packed.x=p0.x; packed.y=p0.y; packed.z=p1.x; packed.w=p1.y;
        *(uint4*)&Cs[(w*16 + r)*NC + n*16 + c] = packed;
        __syncwarp();
    }
    // fused a_src/a_dst dots
    {
        int r = lane>>1, half = lane&1;
        int row = w*16 + r, grow = r0 + row;
        float s=0.f, dd=0.f;
#pragma unroll 8
        for(int c=0;c<32;c++){
            int col = half*32 + c;
            float v = __half2float(Cs[row*64 + col]);
            s += v*__ldg(&atts[col]); dd += v*__ldg(&attd[col]);
        }
        s  += __shfl_xor_sync(0xffffffffu, s, 1);
        dd += __shfl_xor_sync(0xffffffffu, dd, 1);
        if(half==0 && grow < M){ oasrc[grow]=s; oadst[grow]=dd; }
    }
    // store strip
    {
        constexpr int U4 = 16*NC/8;
        const uint4* src = (const uint4*)&Cs[w*16*NC];
        for(int i=lane; i<U4; i+=32){
            int row = (i*8)/NC;
            int grow = r0 + w*16 + row;
            if(grow < M)
                *(uint4*)&C[(size_t)grow*NC + (i*8)%NC] = src[i];
        }
    }
}

// ---------------- 7. fused layer-1: 2 nodes/warp, packed edge records ----------------
#define COMB8(a, u) { \
    float2 fa=__half22float2(*(__half2*)&(u).x), fb=__half22float2(*(__half2*)&(u).y); \
    float2 fc=__half22float2(*(__half2*)&(u).z), fd=__half22float2(*(__half2*)&(u).w); \
    if((a) <= m){ float w_=__expf((a)-m); sden+=w_; \
        acc[0]+=fa.x*w_; acc[1]+=fa.y*w_; acc[2]+=fb.x*w_; acc[3]+=fb.y*w_; \
        acc[4]+=fc.x*w_; acc[5]+=fc.y*w_; acc[6]+=fd.x*w_; acc[7]+=fd.y*w_; } \
    else { float sc=__expf(m-(a)); sden=sden*sc+1.f; \
        acc[0]=acc[0]*sc+fa.x; acc[1]=acc[1]*sc+fa.y; acc[2]=acc[2]*sc+fb.x; acc[3]=acc[3]*sc+fb.y; \
        acc[4]=acc[4]*sc+fc.x; acc[5]=acc[5]*sc+fc.y; acc[6]=acc[6]*sc+fd.x; acc[7]=acc[7]*sc+fd.y; m=(a);} }

__device__ __forceinline__ float ae1_of(uint4 rec, int h){
    float2 f01 = __half22float2(*(__half2*)&rec.y);
    float2 f23 = __half22float2(*(__half2*)&rec.z);
    return (h==0)?f01.x:(h==1)?f01.y:(h==2)?f23.x:f23.y;
}

__global__ __launch_bounds__(256) void k_layer1(){
    int lane = threadIdx.x & 31;
    int warp = (blockIdx.x*blockDim.x + threadIdx.x) >> 5;
    int side = lane >> 4, sl = lane & 15;
    int d = warp*2 + side;
    if(d >= Nn) return;
    int beg = g_off[d], end = g_off[d+1];
    int h = sl >> 2;
    float adst = __ldg(&g_adst1[d*4+h]);
    float m = -1e30f, sden = 0.f;
    float acc[8] = {0.f,0.f,0.f,0.f,0.f,0.f,0.f,0.f};
    int i = beg;
    for(; i+4 <= end; i+=4){
        uint4 r0=__ldg(&g_edge[i+0]), r1=__ldg(&g_edge[i+1]),
              r2=__ldg(&g_edge[i+2]), r3=__ldg(&g_edge[i+3]);
        int s0=(int)r0.x, s1=(int)r1.x, s2=(int)r2.x, s3=(int)r3.x;
        float a0=lrelu(__ldg(&g_asrc1[s0*4+h])+adst+ae1_of(r0,h));
        float a1=lrelu(__ldg(&g_asrc1[s1*4+h])+adst+ae1_of(r1,h));
        float a2=lrelu(__ldg(&g_asrc1[s2*4+h])+adst+ae1_of(r2,h));
        float a3=lrelu(__ldg(&g_asrc1[s3*4+h])+adst+ae1_of(r3,h));
        uint4 v0=__ldg((const uint4*)&g_h1[(size_t)s0*128+sl*8]);
        uint4 v1=__ldg((const uint4*)&g_h1[(size_t)s1*128+sl*8]);
        uint4 v2=__ldg((const uint4*)&g_h1[(size_t)s2*128+sl*8]);
        uint4 v3=__ldg((const uint4*)&g_h1[(size_t)s3*128+sl*8]);
        COMB8(a0,v0); COMB8(a1,v1); COMB8(a2,v2); COMB8(a3,v3);
    }
    for(; i<end; i++){
        uint4 r = __ldg(&g_edge[i]);
        int s = (int)r.x;
        float a = lrelu(__ldg(&g_asrc1[s*4+h])+adst+ae1_of(r,h));
        uint4 hv = __ldg((const uint4*)&g_h1[(size_t)s*128+sl*8]);
        COMB8(a,hv);
    }
    float inv = 1.f/sden;
    __half2 o[4];
#pragma unroll
    for(int j=0;j<4;j++)
        o[j] = __float22half2_rn(make_float2(acc[2*j]*inv, acc[2*j+1]*inv));
    *(uint4*)&g_out1[(size_t)d*128 + sl*8] = *(uint4*)o;
}

// ---------------- 8. fused layer-2 + pool: 2 nodes/warp, packed records ----------------
#define COMB4(a, u) { \
    float2 fa=__half22float2(*(__half2*)&(u).x), fb=__half22float2(*(__half2*)&(u).y); \
    if((a) <= m){ float w_=__expf((a)-m); sden+=w_; \
        acc[0]+=fa.x*w_; acc[1]+=fa.y*w_; acc[2]+=fb.x*w_; acc[3]+=fb.y*w_; } \
    else { float sc=__expf(m-(a)); sden=sden*sc+1.f; \
        acc[0]=acc[0]*sc+fa.x; acc[1]=acc[1]*sc+fa.y; acc[2]=acc[2]*sc+fb.x; acc[3]=acc[3]*sc+fb.y; m=(a);} }

__global__ __launch_bounds__(256) void k_layer2(const int* __restrict__ batch){
    int lane = threadIdx.x & 31;
    int warp = (blockIdx.x*blockDim.x + threadIdx.x) >> 5;
    int side = lane >> 4, sl = lane & 15;
    int d = warp*2 + side;
    if(d >= Nn) return;
    int beg = g_off[d], end = g_off[d+1];
    float adst = __ldg(&g_adst2[d]);
    float m = -1e30f, sden = 0.f;
    float acc[4] = {0.f,0.f,0.f,0.f};
    int i = beg;
    for(; i+4 <= end; i+=4){
        uint4 r0=__ldg(&g_edge[i+0]), r1=__ldg(&g_edge[i+1]),
              r2=__ldg(&g_edge[i+2]), r3=__ldg(&g_edge[i+3]);
        int s0=(int)r0.x, s1=(int)r1.x, s2=(int)r2.x, s3=(int)r3.x;
        float a0=lrelu(__ldg(&g_asrc2[s0])+adst+__low2float(*(__half2*)&r0.w));
        float a1=lrelu(__ldg(&g_asrc2[s1])+adst+__low2float(*(__half2*)&r1.w));
        float a2=lrelu(__ldg(&g_asrc2[s2])+adst+__low2float(*(__half2*)&r2.w));
        float a3=lrelu(__ldg(&g_asrc2[s3])+adst+__low2float(*(__half2*)&r3.w));
        uint2 v0=__ldg((const uint2*)&g_h2[(size_t)s0*64+sl*4]);
        uint2 v1=__ldg((const uint2*)&g_h2[(size_t)s1*64+sl*4]);
        uint2 v2=__ldg((const uint2*)&g_h2[(size_t)s2*64+sl*4]);
        uint2 v3=__ldg((const uint2*)&g_h2[(size_t)s3*64+sl*4]);
        COMB4(a0,v0); COMB4(a1,v1); COMB4(a2,v2); COMB4(a3,v3);
    }
    for(; i<end; i++){
        uint4 r = __ldg(&g_edge[i]);
        int s = (int)r.x;
        float a = lrelu(__ldg(&g_asrc2[s])+adst+__low2float(*(__half2*)&r.w));
        uint2 hv = __ldg((const uint2*)&g_h2[(size_t)s*64+sl*4]);
        COMB4(a,hv);
    }
    float inv = 1.f/sden;
    int g = __ldg(&batch[d]);
    atomicAdd((float4*)&g_pool[g*64 + sl*4],
              make_float4(acc[0]*inv, acc[1]*inv, acc[2]*inv, acc[3]*inv));
    if(sl==0) atomicAdd(&g_cnt[g], 1);
}

// ---------------- 9. final ----------------
__global__ void k_final(float* __restrict__ out, const float* __restrict__ b2){
    int i = blockIdx.x*blockDim.x + threadIdx.x;
    if(i >= Gg*64) return;
    out[i] = g_pool[i] / fmaxf((float)g_cnt[i >> 6], 1.0f) + __ldg(&b2[i & 63]);
}

// ---------------- host launcher ----------------
extern "C" void kernel_launch(void* const* d_in, const int* in_sizes, int n_in,
                              void* d_out, int out_size){
    (void)in_sizes; (void)n_in; (void)out_size;
    const float* x     = (const float*)d_in[0];
    const int*   ei    = (const int*)d_in[1];
    const float* ea    = (const float*)d_in[2];
    const int*   batch = (const int*)d_in[3];
    const float* W1    = (const float*)d_in[4];
    const float* as1   = (const float*)d_in[5];
    const float* ad1   = (const float*)d_in[6];
    const float* We1   = (const float*)d_in[7];
    const float* ae1   = (const float*)d_in[8];
    const float* b1    = (const float*)d_in[9];
    const float* W2    = (const float*)d_in[10];
    const float* as2   = (const float*)d_in[11];
    const float* ad2   = (const float*)d_in[12];
    const float* We2   = (const float*)d_in[13];
    const float* ae2   = (const float*)d_in[14];
    const float* b2    = (const float*)d_in[15];
    float*       out   = (float*)d_out;

    void *p_h1,*p_out1,*p_h2,*p_asrc1,*p_adst1,*p_asrc2,*p_adst2;
    cudaGetSymbolAddress(&p_h1,   g_h1);
    cudaGetSymbolAddress(&p_out1, g_out1);
    cudaGetSymbolAddress(&p_h2,   g_h2);
    cudaGetSymbolAddress(&p_asrc1, g_asrc1);
    cudaGetSymbolAddress(&p_adst1, g_adst1);
    cudaGetSymbolAddress(&p_asrc2, g_asrc2);
    cudaGetSymbolAddress(&p_adst2, g_adst2);

    cudaStream_t s2;
    cudaEvent_t evFork, evJoin;
    cudaStreamCreateWithFlags(&s2, cudaStreamNonBlocking);
    cudaEventCreateWithFlags(&evFork, cudaEventDisableTiming);
    cudaEventCreateWithFlags(&evJoin, cudaEventDisableTiming);

    // fork point at capture begin: gemm1 has no dependency on the preproc chain
    cudaEventRecord(evFork, 0);

    k_init<<<(Nn+255)/256, 256>>>(We1, ae1, We2, ae2);   // #1
    k_pass1<<<(EPt+255)/256, 256>>>(ea, ei);             // #2
    k_scan<<<NBLK, 256>>>();                             // #3
    k_scatter<<<(EPt+255)/256, 256>>>(ei);               // #4 (ncu target)

    cudaStreamWaitEvent(s2, evFork, 0);
    k_gemm1<<<(Nn+63)/64, 256, 0, s2>>>(x, W1, as1, ad1,
                        (__half*)p_h1, (float*)p_asrc1, (float*)p_adst1, Nn);  // #5
    cudaEventRecord(evJoin, s2);

    cudaStreamWaitEvent(0, evJoin, 0);
    k_layer1<<<(Nn/2*32+255)/256, 256>>>();              // #6

    k_gemm2<<<(Nn+127)/128, 256>>>((const __half*)p_out1, W2, b1, as2, ad2,
                        (__half*)p_h2, (float*)p_asrc2, (float*)p_adst2, Nn);  // #7
    k_layer2<<<(Nn/2*32+255)/256, 256>>>(batch);         // #8

    k_final<<<(Gg*64+255)/256, 256>>>(out, b2);          // #9
}

// round 12
// speedup vs baseline: 1.2389x; 1.2389x over previous
#include <cuda_runtime.h>
#include <cuda_fp16.h>
#include <math.h>

#define Nn   50000
#define Ee   800000
#define EPt  850000   // E + N self loops
#define Gg   64
#define NBLK 49       // ceil(Nn/1024)

// ---------------- scratch ----------------
__device__ __align__(16) __half g_h1  [(size_t)Nn*128];   // fp16 features L1
__device__ __align__(16) __half g_out1[(size_t)Nn*128];   // fp16 layer-1 output
__device__ __align__(16) __half g_h2  [(size_t)Nn*64];    // fp16 features L2
__device__ __align__(16) float  g_asrc1[Nn*4];
__device__ __align__(16) float  g_adst1[Nn*4];
__device__ __align__(16) float  g_asrc2[Nn];
__device__ __align__(16) float  g_adst2[Nn];
__device__ __align__(16) float  g_tae1 [(size_t)Ee*4];
__device__ __align__(16) float  g_tae2 [Ee];
__device__ __align__(16) uint4  g_edge [EPt];   // packed: src | ae1[0:2] | ae1[2:4] | ae2,pad
__device__ __align__(16) int    g_deg  [Nn];
__device__ __align__(16) int    g_off  [Nn+1];
__device__ __align__(16) int    g_cur  [Nn];
__device__ __align__(16) int    g_bsum [NBLK];
__device__ __align__(16) int    g_boff [NBLK];
__device__ __align__(16) float  g_sum_ea[16];
__device__ __align__(16) float  g_v1[64];
__device__ __align__(16) float  g_v2[16];
__device__ __align__(16) float  g_pool[Gg*64];
__device__ __align__(16) int    g_cnt [Gg];

__device__ __forceinline__ float lrelu(float x){ return x > 0.f ? x : 0.2f*x; }

__device__ __forceinline__ unsigned packh2(float a, float b){
    __half2 h = __float22half2_rn(make_float2(a,b));
    return *(unsigned*)&h;
}
__device__ __forceinline__ uint2 pack4f(float4 v){
    uint2 r; r.x = packh2(v.x,v.y); r.y = packh2(v.z,v.w); return r;
}

// ---------------- 1. init: zero scratch + v1/v2 ----------------
__global__ void k_init(const float* __restrict__ We1, const float* __restrict__ ae1,
                       const float* __restrict__ We2, const float* __restrict__ ae2){
    int i = blockIdx.x*blockDim.x + threadIdx.x;
    if(i < Nn){ g_deg[i]=0; g_cur[i]=0; }
    if(i < 16) g_sum_ea[i]=0.f;
    if(i < Gg*64) g_pool[i]=0.f;
    if(i < Gg) g_cnt[i]=0;
    if(blockIdx.x == 0){
        int t = threadIdx.x;
        if(t < 64){
            int h = t >> 4, d = t & 15;
            float s = 0.f;
            for(int c=0;c<32;c++) s += We1[d*128 + h*32 + c] * ae1[h*32 + c];
            g_v1[h*16 + d] = s;
        }
        if(t < 16){
            float s = 0.f;
            for(int c=0;c<64;c++) s += We2[t*64 + c] * ae2[c];
            g_v2[t] = s;
        }
    }
}

// ---------------- 2. pass1: one thread/edge; hist + a_edge dots + sum_ea ----------------
__global__ __launch_bounds__(256) void k_pass1(const float* __restrict__ ea,
                                               const int* __restrict__ ei){
    __shared__ float sv1[64], sv2[16], ssum[16];
    int t = threadIdx.x;
    if(t < 64) sv1[t] = g_v1[t];
    if(t < 16){ sv2[t] = g_v2[t]; ssum[t] = 0.f; }
    __syncthreads();
    int e = blockIdx.x*blockDim.x + t;
    float r[16];
#pragma unroll
    for(int i=0;i<16;i++) r[i]=0.f;
    if(e < EPt){
        int d = (e < Ee) ? __ldg(&ei[Ee + e]) : (e - Ee);
        atomicAdd(&g_deg[d], 1);
    }
    if(e < Ee){
        const float4* rp = (const float4*)(ea + (size_t)e*16);
        ((float4*)r)[0]=__ldg(rp);   ((float4*)r)[1]=__ldg(rp+1);
        ((float4*)r)[2]=__ldg(rp+2); ((float4*)r)[3]=__ldg(rp+3);
        float ae[4];
#pragma unroll
        for(int h=0;h<4;h++){
            float a=0.f;
#pragma unroll
            for(int i=0;i<16;i++) a += sv1[h*16+i]*r[i];
            ae[h]=a;
        }
        float a2=0.f;
#pragma unroll
        for(int i=0;i<16;i++) a2 += sv2[i]*r[i];
        *(float4*)&g_tae1[(size_t)e*4] = make_float4(ae[0],ae[1],ae[2],ae[3]);
        g_tae2[e] = a2;
    }
#pragma unroll
    for(int off=16; off; off>>=1)
#pragma unroll
        for(int i=0;i<16;i++) r[i] += __shfl_xor_sync(0xffffffffu, r[i], off);
    if((t & 31)==0)
#pragma unroll
        for(int i=0;i<16;i++) atomicAdd(&ssum[i], r[i]);
    __syncthreads();
    if(t < 16) atomicAdd(&g_sum_ea[t], ssum[t]);
}

// ---------------- 3. scan (3 kernels, measured-fast version) ----------------
__global__ void k_scanA(){
    __shared__ int wsum[8], wexc[8];
    int t = threadIdx.x, blk = blockIdx.x;
    int base = blk*1024 + t*4;
    int v0 = (base+0<Nn)?g_deg[base+0]:0;
    int v1 = (base+1<Nn)?g_deg[base+1]:0;
    int v2 = (base+2<Nn)?g_deg[base+2]:0;
    int v3 = (base+3<Nn)?g_deg[base+3]:0;
    int s = v0+v1+v2+v3;
    int lane = t&31, w = t>>5;
    int ps = s;
#pragma unroll
    for(int off=1; off<32; off<<=1){
        int n = __shfl_up_sync(0xffffffffu, ps, off);
        if(lane>=off) ps += n;
    }
    if(lane==31) wsum[w] = ps;
    __syncthreads();
    if(t==0){
        int r=0;
#pragma unroll
        for(int k=0;k<8;k++){ wexc[k]=r; r+=wsum[k]; }
        g_bsum[blk]=r;
    }
    __syncthreads();
    int run = wexc[w] + ps - s;
    if(base+0<Nn) g_off[base+0]=run; run+=v0;
    if(base+1<Nn) g_off[base+1]=run; run+=v1;
    if(base+2<Nn) g_off[base+2]=run; run+=v2;
    if(base+3<Nn) g_off[base+3]=run;
}
__global__ void k_scanB(){
    if(threadIdx.x==0){
        int r=0;
        for(int b=0;b<NBLK;b++){ g_boff[b]=r; r+=g_bsum[b]; }
        g_off[Nn]=EPt;
    }
}
__global__ void k_scanC(){
    int blk = blockIdx.x;
    if(blk==0) return;
    int add = g_boff[blk];
    int base = blk*1024 + threadIdx.x*4;
#pragma unroll
    for(int j=0;j<4;j++)
        if(base+j < Nn) g_off[base+j] += add;
}

// ---------------- 4. scatter: packed 16-B edge records; inline self-loop lae ----------------
__global__ __launch_bounds__(256) void k_scatter(const int* __restrict__ ei){
    __shared__ float sv1[64], sv2[16], smean[16];
    int t = threadIdx.x;
    if(t < 64) sv1[t] = g_v1[t];
    if(t < 16){ sv2[t] = g_v2[t]; smean[t] = g_sum_ea[t] * (1.0f/(float)Ee); }
    __syncthreads();
    int e = blockIdx.x*blockDim.x + t;
    if(e >= EPt) return;
    int s, d; uint4 rec;
    if(e < Ee){
        s = __ldg(&ei[e]); d = __ldg(&ei[Ee + e]);
        float4 ae = *(const float4*)&g_tae1[(size_t)e*4];
        float ae2 = g_tae2[e];
        uint2 p = pack4f(ae);
        rec.x = (unsigned)s; rec.y = p.x; rec.z = p.y; rec.w = packh2(ae2, 0.f);
    } else {
        s = d = e - Ee;
        float ae[4];
#pragma unroll
        for(int h=0;h<4;h++){
            float a=0.f;
#pragma unroll
            for(int i=0;i<16;i++) a += smean[i]*sv1[h*16+i];
            ae[h]=a;
        }
        float a2=0.f;
#pragma unroll
        for(int i=0;i<16;i++) a2 += smean[i]*sv2[i];
        rec.x = (unsigned)s;
        rec.y = packh2(ae[0],ae[1]); rec.z = packh2(ae[2],ae[3]);
        rec.w = packh2(a2, 0.f);
    }
    int pos = g_off[d] + atomicAdd(&g_cur[d], 1);
    g_edge[pos] = rec;
}

// ---------------- 5. SGEMM (K=128), templated A dtype, fp16 C out, fused epilogue ----------------
template<int NC, bool ELU, typename TA>
__global__ __launch_bounds__(256) void k_gemm(const TA* __restrict__ A,
                                              const float* __restrict__ W,
                                              const float* __restrict__ abias,
                                              const float* __restrict__ atts,
                                              const float* __restrict__ attd,
                                              __half* __restrict__ C,
                                              float* __restrict__ oasrc,
                                              float* __restrict__ oadst, int M){
    constexpr int CPT = NC/16;
    __shared__ float As[64*36];
    __shared__ float Ws[32*NC];
    __shared__ float as_s[NC], ad_s[NC];
    const int t  = threadIdx.x;
    const int rg = t >> 4, cg = t & 15;
    const int r0 = blockIdx.x * 64;
    if(t < NC){ as_s[t]=__ldg(&atts[t]); ad_s[t]=__ldg(&attd[t]); }
    float acc[4][CPT];
#pragma unroll
    for(int i=0;i<4;i++)
#pragma unroll
        for(int j=0;j<CPT;j++) acc[i][j]=0.f;

    for(int kc=0; kc<128; kc+=32){
        if constexpr (!ELU){
#pragma unroll
            for(int i=0;i<2;i++){
                int f = t + i*256; int r = f>>3; int c4 = f&7;
                float4 v = make_float4(0.f,0.f,0.f,0.f);
                if(r0 + r < M) v = __ldg((const float4*)&((const float*)A)[(size_t)(r0+r)*128 + kc + c4*4]);
                float* dst = &As[r*36 + c4*4];
                dst[0]=v.x; dst[1]=v.y; dst[2]=v.z; dst[3]=v.w;
            }
        } else {
            int r = t>>2, c8 = (t&3)*8;
            float f[8] = {0,0,0,0,0,0,0,0};
            if(r0 + r < M){
                uint4 u = __ldg((const uint4*)&((const __half*)A)[(size_t)(r0+r)*128 + kc + c8]);
                float2 a0=__half22float2(*(__half2*)&u.x), a1=__half22float2(*(__half2*)&u.y);
                float2 a2=__half22float2(*(__half2*)&u.z), a3=__half22float2(*(__half2*)&u.w);
                f[0]=a0.x; f[1]=a0.y; f[2]=a1.x; f[3]=a1.y;
                f[4]=a2.x; f[5]=a2.y; f[6]=a3.x; f[7]=a3.y;
                float4 b0 = __ldg((const float4*)&abias[kc+c8]);
                float4 b1 = __ldg((const float4*)&abias[kc+c8+4]);
                f[0]+=b0.x; f[1]+=b0.y; f[2]+=b0.z; f[3]+=b0.w;
                f[4]+=b1.x; f[5]+=b1.y; f[6]+=b1.z; f[7]+=b1.w;
#pragma unroll
                for(int j=0;j<8;j++) f[j] = f[j]>0.f ? f[j] : expm1f(f[j]);
            }
            float* dst = &As[r*36 + c8];
#pragma unroll
            for(int j=0;j<8;j++) dst[j]=f[j];
        }
#pragma unroll
        for(int f=t; f < 32*NC/4; f += 256){
            int k = f/(NC/4); int c = f%(NC/4);
            *(float4*)&Ws[k*NC + c*4] = __ldg((const float4*)&W[(size_t)(kc+k)*NC + c*4]);
        }
        __syncthreads();
#pragma unroll 4
        for(int kk=0; kk<32; kk++){
            float a0 = As[(rg*4+0)*36+kk];
            float a1 = As[(rg*4+1)*36+kk];
            float a2 = As[(rg*4+2)*36+kk];
            float a3 = As[(rg*4+3)*36+kk];
            float4 b0 = *(const float4*)&Ws[kk*NC + cg*CPT];
            acc[0][0]+=a0*b0.x; acc[0][1]+=a0*b0.y; acc[0][2]+=a0*b0.z; acc[0][3]+=a0*b0.w;
            acc[1][0]+=a1*b0.x; acc[1][1]+=a1*b0.y; acc[1][2]+=a1*b0.z; acc[1][3]+=a1*b0.w;
            acc[2][0]+=a2*b0.x; acc[2][1]+=a2*b0.y; acc[2][2]+=a2*b0.z; acc[2][3]+=a2*b0.w;
            acc[3][0]+=a3*b0.x; acc[3][1]+=a3*b0.y; acc[3][2]+=a3*b0.z; acc[3][3]+=a3*b0.w;
            if constexpr (CPT == 8){
                float4 b1 = *(const float4*)&Ws[kk*NC + cg*CPT + 4];
                acc[0][4]+=a0*b1.x; acc[0][5]+=a0*b1.y; acc[0][6]+=a0*b1.z; acc[0][7]+=a0*b1.w;
                acc[1][4]+=a1*b1.x; acc[1][5]+=a1*b1.y; acc[1][6]+=a1*b1.z; acc[1][7]+=a1*b1.w;
                acc[2][4]+=a2*b1.x; acc[2][5]+=a2*b1.y; acc[2][6]+=a2*b1.z; acc[2][7]+=a2*b1.w;
                acc[3][4]+=a3*b1.x; acc[3][5]+=a3*b1.y; acc[3][6]+=a3*b1.z; acc[3][7]+=a3*b1.w;
            }
        }
        __syncthreads();
    }
#pragma unroll
    for(int i=0;i<4;i++){
        int row = r0 + rg*4 + i;
        float ps=0.f, pd=0.f;
#pragma unroll
        for(int j=0;j<CPT;j++){
            float a = acc[i][j];
            ps += a*as_s[cg*CPT+j]; pd += a*ad_s[cg*CPT+j];
        }
        if constexpr (NC == 128){
            ps += __shfl_xor_sync(0xffffffffu, ps, 1); pd += __shfl_xor_sync(0xffffffffu, pd, 1);
            ps += __shfl_xor_sync(0xffffffffu, ps, 2); pd += __shfl_xor_sync(0xffffffffu, pd, 2);
            if((cg&3)==0 && row<M){ oasrc[row*4+(cg>>2)]=ps; oadst[row*4+(cg>>2)]=pd; }
        } else {
            ps += __shfl_xor_sync(0xffffffffu, ps, 1); pd += __shfl_xor_sync(0xffffffffu, pd, 1);
            ps += __shfl_xor_sync(0xffffffffu, ps, 2); pd += __shfl_xor_sync(0xffffffffu, pd, 2);
            ps += __shfl_xor_sync(0xffffffffu, ps, 4); pd += __shfl_xor_sync(0xffffffffu, pd, 4);
            ps += __shfl_xor_sync(0xffffffffu, ps, 8); pd += __shfl_xor_sync(0xffffffffu, pd, 8);
            if(cg==0 && row<M){ oasrc[row]=ps; oadst[row]=pd; }
        }
        if(row < M){
            __half2 hh[CPT/2];
#pragma unroll
            for(int j=0;j<CPT/2;j++)
                hh[j] = __float22half2_rn(make_float2(acc[i][2*j], acc[i][2*j+1]));
            if constexpr (CPT == 8)
                *(uint4*)&C[(size_t)row*NC + cg*CPT] = *(uint4*)hh;
            else
                *(uint2*)&C[(size_t)row*NC + cg*CPT] = *(uint2*)hh;
        }
    }
}

// ---------------- 6. fused layer-1: 2 nodes/warp, packed edge records ----------------
#define COMB8(a, u) { \
    float2 fa=__half22float2(*(__half2*)&(u).x), fb=__half22float2(*(__half2*)&(u).y); \
    float2 fc=__half22float2(*(__half2*)&(u).z), fd=__half22float2(*(__half2*)&(u).w); \
    if((a) <= m){ float w_=__expf((a)-m); sden+=w_; \
        acc[0]+=fa.x*w_; acc[1]+=fa.y*w_; acc[2]+=fb.x*w_; acc[3]+=fb.y*w_; \
        acc[4]+=fc.x*w_; acc[5]+=fc.y*w_; acc[6]+=fd.x*w_; acc[7]+=fd.y*w_; } \
    else { float sc=__expf(m-(a)); sden=sden*sc+1.f; \
        acc[0]=acc[0]*sc+fa.x; acc[1]=acc[1]*sc+fa.y; acc[2]=acc[2]*sc+fb.x; acc[3]=acc[3]*sc+fb.y; \
        acc[4]=acc[4]*sc+fc.x; acc[5]=acc[5]*sc+fc.y; acc[6]=acc[6]*sc+fd.x; acc[7]=acc[7]*sc+fd.y; m=(a);} }

__device__ __forceinline__ float ae1_of(uint4 rec, int h){
    float2 f01 = __half22float2(*(__half2*)&rec.y);
    float2 f23 = __half22float2(*(__half2*)&rec.z);
    return (h==0)?f01.x:(h==1)?f01.y:(h==2)?f23.x:f23.y;
}

__global__ __launch_bounds__(256) void k_layer1(){
    int lane = threadIdx.x & 31;
    int warp = (blockIdx.x*blockDim.x + threadIdx.x) >> 5;
    int side = lane >> 4, sl = lane & 15;
    int d = warp*2 + side;
    if(d >= Nn) return;
    int beg = g_off[d], end = g_off[d+1];
    int h = sl >> 2;
    float adst = __ldg(&g_adst1[d*4+h]);
    float m = -1e30f, sden = 0.f;
    float acc[8] = {0.f,0.f,0.f,0.f,0.f,0.f,0.f,0.f};
    int i = beg;
    for(; i+4 <= end; i+=4){
        uint4 r0=__ldg(&g_edge[i+0]), r1=__ldg(&g_edge[i+1]),
              r2=__ldg(&g_edge[i+2]), r3=__ldg(&g_edge[i+3]);
        int s0=(int)r0.x, s1=(int)r1.x, s2=(int)r2.x, s3=(int)r3.x;
        float a0=lrelu(__ldg(&g_asrc1[s0*4+h])+adst+ae1_of(r0,h));
        float a1=lrelu(__ldg(&g_asrc1[s1*4+h])+adst+ae1_of(r1,h));
        float a2=lrelu(__ldg(&g_asrc1[s2*4+h])+adst+ae1_of(r2,h));
        float a3=lrelu(__ldg(&g_asrc1[s3*4+h])+adst+ae1_of(r3,h));
        uint4 v0=__ldg((const uint4*)&g_h1[(size_t)s0*128+sl*8]);
        uint4 v1=__ldg((const uint4*)&g_h1[(size_t)s1*128+sl*8]);
        uint4 v2=__ldg((const uint4*)&g_h1[(size_t)s2*128+sl*8]);
        uint4 v3=__ldg((const uint4*)&g_h1[(size_t)s3*128+sl*8]);
        COMB8(a0,v0); COMB8(a1,v1); COMB8(a2,v2); COMB8(a3,v3);
    }
    for(; i<end; i++){
        uint4 r = __ldg(&g_edge[i]);
        int s = (int)r.x;
        float a = lrelu(__ldg(&g_asrc1[s*4+h])+adst+ae1_of(r,h));
        uint4 hv = __ldg((const uint4*)&g_h1[(size_t)s*128+sl*8]);
        COMB8(a,hv);
    }
    float inv = 1.f/sden;
    __half2 o[4];
#pragma unroll
    for(int j=0;j<4;j++)
        o[j] = __float22half2_rn(make_float2(acc[2*j]*inv, acc[2*j+1]*inv));
    *(uint4*)&g_out1[(size_t)d*128 + sl*8] = *(uint4*)o;
}

// ---------------- 7. fused layer-2 + pool: 2 nodes/warp, packed records ----------------
#define COMB4(a, u) { \
    float2 fa=__half22float2(*(__half2*)&(u).x), fb=__half22float2(*(__half2*)&(u).y); \
    if((a) <= m){ float w_=__expf((a)-m); sden+=w_; \
        acc[0]+=fa.x*w_; acc[1]+=fa.y*w_; acc[2]+=fb.x*w_; acc[3]+=fb.y*w_; } \
    else { float sc=__expf(m-(a)); sden=sden*sc+1.f; \
        acc[0]=acc[0]*sc+fa.x; acc[1]=acc[1]*sc+fa.y; acc[2]=acc[2]*sc+fb.x; acc[3]=acc[3]*sc+fb.y; m=(a);} }

__global__ __launch_bounds__(256) void k_layer2(const int* __restrict__ batch){
    int lane = threadIdx.x & 31;
    int warp = (blockIdx.x*blockDim.x + threadIdx.x) >> 5;
    int side = lane >> 4, sl = lane & 15;
    int d = warp*2 + side;
    if(d >= Nn) return;
    int beg = g_off[d], end = g_off[d+1];
    float adst = __ldg(&g_adst2[d]);
    float m = -1e30f, sden = 0.f;
    float acc[4] = {0.f,0.f,0.f,0.f};
    int i = beg;
    for(; i+4 <= end; i+=4){
        uint4 r0=__ldg(&g_edge[i+0]), r1=__ldg(&g_edge[i+1]),
              r2=__ldg(&g_edge[i+2]), r3=__ldg(&g_edge[i+3]);
        int s0=(int)r0.x, s1=(int)r1.x, s2=(int)r2.x, s3=(int)r3.x;
        float a0=lrelu(__ldg(&g_asrc2[s0])+adst+__low2float(*(__half2*)&r0.w));
        float a1=lrelu(__ldg(&g_asrc2[s1])+adst+__low2float(*(__half2*)&r1.w));
        float a2=lrelu(__ldg(&g_asrc2[s2])+adst+__low2float(*(__half2*)&r2.w));
        float a3=lrelu(__ldg(&g_asrc2[s3])+adst+__low2float(*(__half2*)&r3.w));
        uint2 v0=__ldg((const uint2*)&g_h2[(size_t)s0*64+sl*4]);
        uint2 v1=__ldg((const uint2*)&g_h2[(size_t)s1*64+sl*4]);
        uint2 v2=__ldg((const uint2*)&g_h2[(size_t)s2*64+sl*4]);
        uint2 v3=__ldg((const uint2*)&g_h2[(size_t)s3*64+sl*4]);
        COMB4(a0,v0); COMB4(a1,v1); COMB4(a2,v2); COMB4(a3,v3);
    }
    for(; i<end; i++){
        uint4 r = __ldg(&g_edge[i]);
        int s = (int)r.x;
        float a = lrelu(__ldg(&g_asrc2[s])+adst+__low2float(*(__half2*)&r.w));
        uint2 hv = __ldg((const uint2*)&g_h2[(size_t)s*64+sl*4]);
        COMB4(a,hv);
    }
    float inv = 1.f/sden;
    int g = __ldg(&batch[d]);
    atomicAdd((float4*)&g_pool[g*64 + sl*4],
              make_float4(acc[0]*inv, acc[1]*inv, acc[2]*inv, acc[3]*inv));
    if(sl==0) atomicAdd(&g_cnt[g], 1);
}

// ---------------- 8. final ----------------
__global__ void k_final(float* __restrict__ out, const float* __restrict__ b2){
    int i = blockIdx.x*blockDim.x + threadIdx.x;
    if(i >= Gg*64) return;
    out[i] = g_pool[i] / fmaxf((float)g_cnt[i >> 6], 1.0f) + __ldg(&b2[i & 63]);
}

// ---------------- host launcher ----------------
extern "C" void kernel_launch(void* const* d_in, const int* in_sizes, int n_in,
                              void* d_out, int out_size){
    (void)in_sizes; (void)n_in; (void)out_size;
    const float* x     = (const float*)d_in[0];
    const int*   ei    = (const int*)d_in[1];
    const float* ea    = (const float*)d_in[2];
    const int*   batch = (const int*)d_in[3];
    const float* W1    = (const float*)d_in[4];
    const float* as1   = (const float*)d_in[5];
    const float* ad1   = (const float*)d_in[6];
    const float* We1   = (const float*)d_in[7];
    const float* ae1   = (const float*)d_in[8];
    const float* b1    = (const float*)d_in[9];
    const float* W2    = (const float*)d_in[10];
    const float* as2   = (const float*)d_in[11];
    const float* ad2   = (const float*)d_in[12];
    const float* We2   = (const float*)d_in[13];
    const float* ae2   = (const float*)d_in[14];
    const float* b2    = (const float*)d_in[15];
    float*       out   = (float*)d_out;

    void *p_h1,*p_out1,*p_h2,*p_asrc1,*p_adst1,*p_asrc2,*p_adst2;
    cudaGetSymbolAddress(&p_h1,   g_h1);
    cudaGetSymbolAddress(&p_out1, g_out1);
    cudaGetSymbolAddress(&p_h2,   g_h2);
    cudaGetSymbolAddress(&p_asrc1, g_asrc1);
    cudaGetSymbolAddress(&p_adst1, g_adst1);
    cudaGetSymbolAddress(&p_asrc2, g_asrc2);
    cudaGetSymbolAddress(&p_adst2, g_adst2);

    cudaStream_t s2;
    cudaEvent_t evFork, evJoin;
    cudaStreamCreateWithFlags(&s2, cudaStreamNonBlocking);
    cudaEventCreateWithFlags(&evFork, cudaEventDisableTiming);
    cudaEventCreateWithFlags(&evJoin, cudaEventDisableTiming);

    // fork point at capture begin: gemm1 has no dependency on the preproc chain
    cudaEventRecord(evFork, 0);

    k_init<<<(Nn+255)/256, 256>>>(We1, ae1, We2, ae2);   // #1
    k_pass1<<<(EPt+255)/256, 256>>>(ea, ei);             // #2
    k_scanA<<<NBLK, 256>>>();                            // #3

    cudaStreamWaitEvent(s2, evFork, 0);
    k_gemm<128,false,float><<<(Nn+63)/64, 256, 0, s2>>>(x, W1, nullptr, as1, ad1,
                        (__half*)p_h1, (float*)p_asrc1, (float*)p_adst1, Nn);  // #4 (ncu target)
    cudaEventRecord(evJoin, s2);

    k_scanB<<<1, 32>>>();                                // #5
    k_scanC<<<NBLK, 256>>>();                            // #6
    k_scatter<<<(EPt+255)/256, 256>>>(ei);               // #7

    cudaStreamWaitEvent(0, evJoin, 0);
    k_layer1<<<(Nn/2*32+255)/256, 256>>>();              // #8

    k_gemm<64,true,__half><<<(Nn+63)/64, 256>>>((const __half*)p_out1, W2, b1, as2, ad2,
                        (__half*)p_h2, (float*)p_asrc2, (float*)p_adst2, Nn);  // #9
    k_layer2<<<(Nn/2*32+255)/256, 256>>>(batch);         // #10

    k_final<<<(Gg*64+255)/256, 256>>>(out, b2);          // #11
}

// round 13
// speedup vs baseline: 1.2847x; 1.0370x over previous
#include <cuda_runtime.h>
#include <cuda_fp16.h>
#include <math.h>

#define Nn   50000
#define Ee   800000
#define EPt  850000   // E + N self loops
#define Gg   64
#define NBLK 49       // ceil(Nn/1024)

// ---------------- scratch ----------------
__device__ __align__(16) __half g_h1  [(size_t)Nn*128];   // fp16 features L1
__device__ __align__(16) __half g_out1[(size_t)Nn*128];   // fp16 layer-1 output
__device__ __align__(16) __half g_h2  [(size_t)Nn*64];    // fp16 features L2
__device__ __align__(16) float  g_asrc1[Nn*4];
__device__ __align__(16) float  g_adst1[Nn*4];
__device__ __align__(16) float  g_asrc2[Nn];
__device__ __align__(16) float  g_adst2[Nn];
__device__ __align__(16) float  g_tae1 [(size_t)Ee*4];
__device__ __align__(16) float  g_tae2 [Ee];
__device__ __align__(16) int    g_ssrc [EPt];
__device__ __align__(16) float  g_sae1 [(size_t)EPt*4];
__device__ __align__(16) float  g_sae2 [EPt];
__device__ __align__(16) int    g_deg  [Nn];
__device__ __align__(16) int    g_off  [Nn+1];
__device__ __align__(16) int    g_cur  [Nn];
__device__ __align__(16) int    g_bsum [NBLK];
__device__ __align__(16) int    g_boff [NBLK];
__device__ __align__(16) float  g_sum_ea[16];
__device__ __align__(16) float  g_v1[64];
__device__ __align__(16) float  g_v2[16];
__device__ __align__(16) float  g_lae1[4];
__device__ __align__(16) float  g_lae2[1];
__device__ __align__(16) float  g_pool[Gg*64];
__device__ __align__(16) int    g_cnt [Gg];

__device__ __forceinline__ float lrelu(float x){ return x > 0.f ? x : 0.2f*x; }

// ---------------- 1. init: zero scratch + v1/v2 ----------------
__global__ void k_init(const float* __restrict__ We1, const float* __restrict__ ae1,
                       const float* __restrict__ We2, const float* __restrict__ ae2){
    int i = blockIdx.x*blockDim.x + threadIdx.x;
    if(i < Nn){ g_deg[i]=0; g_cur[i]=0; }
    if(i < 16) g_sum_ea[i]=0.f;
    if(i < Gg*64) g_pool[i]=0.f;
    if(i < Gg) g_cnt[i]=0;
    if(blockIdx.x == 0){
        int t = threadIdx.x;
        if(t < 64){
            int h = t >> 4, d = t & 15;
            float s = 0.f;
            for(int c=0;c<32;c++) s += We1[d*128 + h*32 + c] * ae1[h*32 + c];
            g_v1[h*16 + d] = s;
        }
        if(t < 16){
            float s = 0.f;
            for(int c=0;c<64;c++) s += We2[t*64 + c] * ae2[c];
            g_v2[t] = s;
        }
    }
}

// ---------------- 2. pass1: one thread/edge; hist + a_edge dots + sum_ea ----------------
__global__ __launch_bounds__(256) void k_pass1(const float* __restrict__ ea,
                                               const int* __restrict__ ei){
    __shared__ float sv1[64], sv2[16], ssum[16];
    int t = threadIdx.x;
    if(t < 64) sv1[t] = g_v1[t];
    if(t < 16){ sv2[t] = g_v2[t]; ssum[t] = 0.f; }
    __syncthreads();
    int e = blockIdx.x*blockDim.x + t;
    float r[16];
#pragma unroll
    for(int i=0;i<16;i++) r[i]=0.f;
    if(e < EPt){
        int d = (e < Ee) ? __ldg(&ei[Ee + e]) : (e - Ee);
        atomicAdd(&g_deg[d], 1);
    }
    if(e < Ee){
        const float4* rp = (const float4*)(ea + (size_t)e*16);
        ((float4*)r)[0]=__ldg(rp);   ((float4*)r)[1]=__ldg(rp+1);
        ((float4*)r)[2]=__ldg(rp+2); ((float4*)r)[3]=__ldg(rp+3);
        float ae[4];
#pragma unroll
        for(int h=0;h<4;h++){
            float a=0.f;
#pragma unroll
            for(int i=0;i<16;i++) a += sv1[h*16+i]*r[i];
            ae[h]=a;
        }
        float a2=0.f;
#pragma unroll
        for(int i=0;i<16;i++) a2 += sv2[i]*r[i];
        *(float4*)&g_tae1[(size_t)e*4] = make_float4(ae[0],ae[1],ae[2],ae[3]);
        g_tae2[e] = a2;
    }
#pragma unroll
    for(int off=16; off; off>>=1)
#pragma unroll
        for(int i=0;i<16;i++) r[i] += __shfl_xor_sync(0xffffffffu, r[i], off);
    if((t & 31)==0)
#pragma unroll
        for(int i=0;i<16;i++) atomicAdd(&ssum[i], r[i]);
    __syncthreads();
    if(t < 16) atomicAdd(&g_sum_ea[t], ssum[t]);
}

// ---------------- 3. scan (3 kernels); lae folded into scanB ----------------
__global__ void k_scanA(){
    __shared__ int wsum[8], wexc[8];
    int t = threadIdx.x, blk = blockIdx.x;
    int base = blk*1024 + t*4;
    int v0 = (base+0<Nn)?g_deg[base+0]:0;
    int v1 = (base+1<Nn)?g_deg[base+1]:0;
    int v2 = (base+2<Nn)?g_deg[base+2]:0;
    int v3 = (base+3<Nn)?g_deg[base+3]:0;
    int s = v0+v1+v2+v3;
    int lane = t&31, w = t>>5;
    int ps = s;
#pragma unroll
    for(int off=1; off<32; off<<=1){
        int n = __shfl_up_sync(0xffffffffu, ps, off);
        if(lane>=off) ps += n;
    }
    if(lane==31) wsum[w] = ps;
    __syncthreads();
    if(t==0){
        int r=0;
#pragma unroll
        for(int k=0;k<8;k++){ wexc[k]=r; r+=wsum[k]; }
        g_bsum[blk]=r;
    }
    __syncthreads();
    int run = wexc[w] + ps - s;
    if(base+0<Nn) g_off[base+0]=run; run+=v0;
    if(base+1<Nn) g_off[base+1]=run; run+=v1;
    if(base+2<Nn) g_off[base+2]=run; run+=v2;
    if(base+3<Nn) g_off[base+3]=run;
}
__global__ void k_scanB(){
    int t = threadIdx.x;
    if(t==0){
        int r=0;
        for(int b=0;b<NBLK;b++){ g_boff[b]=r; r+=g_bsum[b]; }
        g_off[Nn]=EPt;
    }
    if(t>=1 && t<5){
        int h = t-1;
        float s = 0.f;
        for(int d=0;d<16;d++) s += (g_sum_ea[d]*(1.0f/(float)Ee))*g_v1[h*16+d];
        g_lae1[h] = s;
    }
    if(t == 5){
        float s = 0.f;
        for(int d=0;d<16;d++) s += (g_sum_ea[d]*(1.0f/(float)Ee))*g_v2[d];
        g_lae2[0] = s;
    }
}
__global__ void k_scanC(){
    int blk = blockIdx.x;
    if(blk==0) return;
    int add = g_boff[blk];
    int base = blk*1024 + threadIdx.x*4;
#pragma unroll
    for(int j=0;j<4;j++)
        if(base+j < Nn) g_off[base+j] += add;
}

// ---------------- 4. scatter (round-10 layout) ----------------
__global__ void k_scatter(const int* __restrict__ ei){
    int e = blockIdx.x*blockDim.x + threadIdx.x;
    if(e >= EPt) return;
    int s, d; float4 ae; float ae2;
    if(e < Ee){
        s = __ldg(&ei[e]); d = __ldg(&ei[Ee + e]);
        ae = *(const float4*)&g_tae1[(size_t)e*4];
        ae2 = g_tae2[e];
    } else {
        s = d = e - Ee;
        ae = make_float4(g_lae1[0],g_lae1[1],g_lae1[2],g_lae1[3]);
        ae2 = g_lae2[0];
    }
    int pos = g_off[d] + atomicAdd(&g_cur[d], 1);
    g_ssrc[pos] = s;
    *(float4*)&g_sae1[(size_t)pos*4] = ae;
    g_sae2[pos] = ae2;
}

// ---------------- 5. SGEMM (K=128), TRANSPOSED A-tile (LDS.128), fp16 C out ----------------
template<int NC, bool ELU, typename TA>
__global__ __launch_bounds__(256) void k_gemm(const TA* __restrict__ A,
                                              const float* __restrict__ W,
                                              const float* __restrict__ abias,
                                              const float* __restrict__ atts,
                                              const float* __restrict__ attd,
                                              __half* __restrict__ C,
                                              float* __restrict__ oasrc,
                                              float* __restrict__ oadst, int M){
    constexpr int CPT = NC/16;
    constexpr int AST = 68;                    // transposed-A row stride (floats, mult of 4)
    __shared__ float AsT[32*AST];              // [kk][row]
    __shared__ float Ws[32*NC];
    __shared__ float as_s[NC], ad_s[NC];
    const int t  = threadIdx.x;
    const int rg = t >> 4, cg = t & 15;
    const int r0 = blockIdx.x * 64;
    if(t < NC){ as_s[t]=__ldg(&atts[t]); ad_s[t]=__ldg(&attd[t]); }
    float acc[4][CPT];
#pragma unroll
    for(int i=0;i<4;i++)
#pragma unroll
        for(int j=0;j<CPT;j++) acc[i][j]=0.f;

    for(int kc=0; kc<128; kc+=32){
        if constexpr (!ELU){
#pragma unroll
            for(int i=0;i<2;i++){
                int f = t + i*256; int r = f>>3; int c4 = f&7;
                float4 v = make_float4(0.f,0.f,0.f,0.f);
                if(r0 + r < M) v = __ldg((const float4*)&((const float*)A)[(size_t)(r0+r)*128 + kc + c4*4]);
                AsT[(c4*4+0)*AST + r] = v.x;
                AsT[(c4*4+1)*AST + r] = v.y;
                AsT[(c4*4+2)*AST + r] = v.z;
                AsT[(c4*4+3)*AST + r] = v.w;
            }
        } else {
            int r = t>>2, c8 = (t&3)*8;
            float f[8] = {0,0,0,0,0,0,0,0};
            if(r0 + r < M){
                uint4 u = __ldg((const uint4*)&((const __half*)A)[(size_t)(r0+r)*128 + kc + c8]);
                float2 a0=__half22float2(*(__half2*)&u.x), a1=__half22float2(*(__half2*)&u.y);
                float2 a2=__half22float2(*(__half2*)&u.z), a3=__half22float2(*(__half2*)&u.w);
                f[0]=a0.x; f[1]=a0.y; f[2]=a1.x; f[3]=a1.y;
                f[4]=a2.x; f[5]=a2.y; f[6]=a3.x; f[7]=a3.y;
                float4 b0 = __ldg((const float4*)&abias[kc+c8]);
                float4 b1 = __ldg((const float4*)&abias[kc+c8+4]);
                f[0]+=b0.x; f[1]+=b0.y; f[2]+=b0.z; f[3]+=b0.w;
                f[4]+=b1.x; f[5]+=b1.y; f[6]+=b1.z; f[7]+=b1.w;
#pragma unroll
                for(int j=0;j<8;j++) f[j] = f[j]>0.f ? f[j] : expm1f(f[j]);
            }
#pragma unroll
            for(int j=0;j<8;j++) AsT[(c8+j)*AST + r] = f[j];
        }
#pragma unroll
        for(int f=t; f < 32*NC/4; f += 256){
            int k = f/(NC/4); int c = f%(NC/4);
            *(float4*)&Ws[k*NC + c*4] = __ldg((const float4*)&W[(size_t)(kc+k)*NC + c*4]);
        }
        __syncthreads();
#pragma unroll 4
        for(int kk=0; kk<32; kk++){
            float4 a = *(const float4*)&AsT[kk*AST + rg*4];
            float4 b0 = *(const float4*)&Ws[kk*NC + cg*CPT];
            acc[0][0]+=a.x*b0.x; acc[0][1]+=a.x*b0.y; acc[0][2]+=a.x*b0.z; acc[0][3]+=a.x*b0.w;
            acc[1][0]+=a.y*b0.x; acc[1][1]+=a.y*b0.y; acc[1][2]+=a.y*b0.z; acc[1][3]+=a.y*b0.w;
            acc[2][0]+=a.z*b0.x; acc[2][1]+=a.z*b0.y; acc[2][2]+=a.z*b0.z; acc[2][3]+=a.z*b0.w;
            acc[3][0]+=a.w*b0.x; acc[3][1]+=a.w*b0.y; acc[3][2]+=a.w*b0.z; acc[3][3]+=a.w*b0.w;
            if constexpr (CPT == 8){
                float4 b1 = *(const float4*)&Ws[kk*NC + cg*CPT + 4];
                acc[0][4]+=a.x*b1.x; acc[0][5]+=a.x*b1.y; acc[0][6]+=a.x*b1.z; acc[0][7]+=a.x*b1.w;
                acc[1][4]+=a.y*b1.x; acc[1][5]+=a.y*b1.y; acc[1][6]+=a.y*b1.z; acc[1][7]+=a.y*b1.w;
                acc[2][4]+=a.z*b1.x; acc[2][5]+=a.z*b1.y; acc[2][6]+=a.z*b1.z; acc[2][7]+=a.z*b1.w;
                acc[3][4]+=a.w*b1.x; acc[3][5]+=a.w*b1.y; acc[3][6]+=a.w*b1.z; acc[3][7]+=a.w*b1.w;
            }
        }
        __syncthreads();
    }
#pragma unroll
    for(int i=0;i<4;i++){
        int row = r0 + rg*4 + i;
        float ps=0.f, pd=0.f;
#pragma unroll
        for(int j=0;j<CPT;j++){
            float a = acc[i][j];
            ps += a*as_s[cg*CPT+j]; pd += a*ad_s[cg*CPT+j];
        }
        if constexpr (NC == 128){
            ps += __shfl_xor_sync(0xffffffffu, ps, 1); pd += __shfl_xor_sync(0xffffffffu, pd, 1);
            ps += __shfl_xor_sync(0xffffffffu, ps, 2); pd += __shfl_xor_sync(0xffffffffu, pd, 2);
            if((cg&3)==0 && row<M){ oasrc[row*4+(cg>>2)]=ps; oadst[row*4+(cg>>2)]=pd; }
        } else {
            ps += __shfl_xor_sync(0xffffffffu, ps, 1); pd += __shfl_xor_sync(0xffffffffu, pd, 1);
            ps += __shfl_xor_sync(0xffffffffu, ps, 2); pd += __shfl_xor_sync(0xffffffffu, pd, 2);
            ps += __shfl_xor_sync(0xffffffffu, ps, 4); pd += __shfl_xor_sync(0xffffffffu, pd, 4);
            ps += __shfl_xor_sync(0xffffffffu, ps, 8); pd += __shfl_xor_sync(0xffffffffu, pd, 8);
            if(cg==0 && row<M){ oasrc[row]=ps; oadst[row]=pd; }
        }
        if(row < M){
            __half2 hh[CPT/2];
#pragma unroll
            for(int j=0;j<CPT/2;j++)
                hh[j] = __float22half2_rn(make_float2(acc[i][2*j], acc[i][2*j+1]));
            if constexpr (CPT == 8)
                *(uint4*)&C[(size_t)row*NC + cg*CPT] = *(uint4*)hh;
            else
                *(uint2*)&C[(size_t)row*NC + cg*CPT] = *(uint2*)hh;
        }
    }
}

// ---------------- 6. fused layer-1: 2 nodes/warp (round-10 layout) ----------------
#define COMB8(a, u) { \
    float2 fa=__half22float2(*(__half2*)&(u).x), fb=__half22float2(*(__half2*)&(u).y); \
    float2 fc=__half22float2(*(__half2*)&(u).z), fd=__half22float2(*(__half2*)&(u).w); \
    if((a) <= m){ float w_=__expf((a)-m); sden+=w_; \
        acc[0]+=fa.x*w_; acc[1]+=fa.y*w_; acc[2]+=fb.x*w_; acc[3]+=fb.y*w_; \
        acc[4]+=fc.x*w_; acc[5]+=fc.y*w_; acc[6]+=fd.x*w_; acc[7]+=fd.y*w_; } \
    else { float sc=__expf(m-(a)); sden=sden*sc+1.f; \
        acc[0]=acc[0]*sc+fa.x; acc[1]=acc[1]*sc+fa.y; acc[2]=acc[2]*sc+fb.x; acc[3]=acc[3]*sc+fb.y; \
        acc[4]=acc[4]*sc+fc.x; acc[5]=acc[5]*sc+fc.y; acc[6]=acc[6]*sc+fd.x; acc[7]=acc[7]*sc+fd.y; m=(a);} }

__global__ __launch_bounds__(256) void k_layer1(){
    int lane = threadIdx.x & 31;
    int warp = (blockIdx.x*blockDim.x + threadIdx.x) >> 5;
    int side = lane >> 4, sl = lane & 15;
    int d = warp*2 + side;
    if(d >= Nn) return;
    int beg = g_off[d], end = g_off[d+1];
    int h = sl >> 2;
    float adst = __ldg(&g_adst1[d*4+h]);
    float m = -1e30f, sden = 0.f;
    float acc[8] = {0.f,0.f,0.f,0.f,0.f,0.f,0.f,0.f};
    int i = beg;
    for(; i+4 <= end; i+=4){
        int s0=__ldg(&g_ssrc[i+0]), s1=__ldg(&g_ssrc[i+1]),
            s2=__ldg(&g_ssrc[i+2]), s3=__ldg(&g_ssrc[i+3]);
        float e0=__ldg(&g_sae1[(size_t)(i+0)*4+h]), e1=__ldg(&g_sae1[(size_t)(i+1)*4+h]),
              e2=__ldg(&g_sae1[(size_t)(i+2)*4+h]), e3=__ldg(&g_sae1[(size_t)(i+3)*4+h]);
        float a0=lrelu(__ldg(&g_asrc1[s0*4+h])+adst+e0);
        float a1=lrelu(__ldg(&g_asrc1[s1*4+h])+adst+e1);
        float a2=lrelu(__ldg(&g_asrc1[s2*4+h])+adst+e2);
        float a3=lrelu(__ldg(&g_asrc1[s3*4+h])+adst+e3);
        uint4 v0=__ldg((const uint4*)&g_h1[(size_t)s0*128+sl*8]);
        uint4 v1=__ldg((const uint4*)&g_h1[(size_t)s1*128+sl*8]);
        uint4 v2=__ldg((const uint4*)&g_h1[(size_t)s2*128+sl*8]);
        uint4 v3=__ldg((const uint4*)&g_h1[(size_t)s3*128+sl*8]);
        COMB8(a0,v0); COMB8(a1,v1); COMB8(a2,v2); COMB8(a3,v3);
    }
    for(; i<end; i++){
        int s = __ldg(&g_ssrc[i]);
        float a = lrelu(__ldg(&g_asrc1[s*4+h])+adst+__ldg(&g_sae1[(size_t)i*4+h]));
        uint4 hv = __ldg((const uint4*)&g_h1[(size_t)s*128+sl*8]);
        COMB8(a,hv);
    }
    float inv = 1.f/sden;
    __half2 o[4];
#pragma unroll
    for(int j=0;j<4;j++)
        o[j] = __float22half2_rn(make_float2(acc[2*j]*inv, acc[2*j+1]*inv));
    *(uint4*)&g_out1[(size_t)d*128 + sl*8] = *(uint4*)o;
}

// ---------------- 7. fused layer-2 + pool: 2 nodes/warp (round-10 layout) ----------------
#define COMB4(a, u) { \
    float2 fa=__half22float2(*(__half2*)&(u).x), fb=__half22float2(*(__half2*)&(u).y); \
    if((a) <= m){ float w_=__expf((a)-m); sden+=w_; \
        acc[0]+=fa.x*w_; acc[1]+=fa.y*w_; acc[2]+=fb.x*w_; acc[3]+=fb.y*w_; } \
    else { float sc=__expf(m-(a)); sden=sden*sc+1.f; \
        acc[0]=acc[0]*sc+fa.x; acc[1]=acc[1]*sc+fa.y; acc[2]=acc[2]*sc+fb.x; acc[3]=acc[3]*sc+fb.y; m=(a);} }

__global__ __launch_bounds__(256) void k_layer2(const int* __restrict__ batch){
    int lane = threadIdx.x & 31;
    int warp = (blockIdx.x*blockDim.x + threadIdx.x) >> 5;
    int side = lane >> 4, sl = lane & 15;
    int d = warp*2 + side;
    if(d >= Nn) return;
    int beg = g_off[d], end = g_off[d+1];
    float adst = __ldg(&g_adst2[d]);
    float m = -1e30f, sden = 0.f;
    float acc[4] = {0.f,0.f,0.f,0.f};
    int i = beg;
    for(; i+4 <= end; i+=4){
        int s0=__ldg(&g_ssrc[i+0]), s1=__ldg(&g_ssrc[i+1]),
            s2=__ldg(&g_ssrc[i+2]), s3=__ldg(&g_ssrc[i+3]);
        float a0=lrelu(__ldg(&g_asrc2[s0])+adst+__ldg(&g_sae2[i+0]));
        float a1=lrelu(__ldg(&g_asrc2[s1])+adst+__ldg(&g_sae2[i+1]));
        float a2=lrelu(__ldg(&g_asrc2[s2])+adst+__ldg(&g_sae2[i+2]));
        float a3=lrelu(__ldg(&g_asrc2[s3])+adst+__ldg(&g_sae2[i+3]));
        uint2 v0=__ldg((const uint2*)&g_h2[(size_t)s0*64+sl*4]);
        uint2 v1=__ldg((const uint2*)&g_h2[(size_t)s1*64+sl*4]);
        uint2 v2=__ldg((const uint2*)&g_h2[(size_t)s2*64+sl*4]);
        uint2 v3=__ldg((const uint2*)&g_h2[(size_t)s3*64+sl*4]);
        COMB4(a0,v0); COMB4(a1,v1); COMB4(a2,v2); COMB4(a3,v3);
    }
    for(; i<end; i++){
        int s = __ldg(&g_ssrc[i]);
        float a = lrelu(__ldg(&g_asrc2[s])+adst+__ldg(&g_sae2[i]));
        uint2 hv = __ldg((const uint2*)&g_h2[(size_t)s*64+sl*4]);
        COMB4(a,hv);
    }
    float inv = 1.f/sden;
    int g = __ldg(&batch[d]);
    atomicAdd((float4*)&g_pool[g*64 + sl*4],
              make_float4(acc[0]*inv, acc[1]*inv, acc[2]*inv, acc[3]*inv));
    if(sl==0) atomicAdd(&g_cnt[g], 1);
}

// ---------------- 8. final ----------------
__global__ void k_final(float* __restrict__ out, const float* __restrict__ b2){
    int i = blockIdx.x*blockDim.x + threadIdx.x;
    if(i >= Gg*64) return;
    out[i] = g_pool[i] / fmaxf((float)g_cnt[i >> 6], 1.0f) + __ldg(&b2[i & 63]);
}

// ---------------- host launcher ----------------
extern "C" void kernel_launch(void* const* d_in, const int* in_sizes, int n_in,
                              void* d_out, int out_size){
    (void)in_sizes; (void)n_in; (void)out_size;
    const float* x     = (const float*)d_in[0];
    const int*   ei    = (const int*)d_in[1];
    const float* ea    = (const float*)d_in[2];
    const int*   batch = (const int*)d_in[3];
    const float* W1    = (const float*)d_in[4];
    const float* as1   = (const float*)d_in[5];
    const float* ad1   = (const float*)d_in[6];
    const float* We1   = (const float*)d_in[7];
    const float* ae1   = (const float*)d_in[8];
    const float* b1    = (const float*)d_in[9];
    const float* W2    = (const float*)d_in[10];
    const float* as2   = (const float*)d_in[11];
    const float* ad2   = (const float*)d_in[12];
    const float* We2   = (const float*)d_in[13];
    const float* ae2   = (const float*)d_in[14];
    const float* b2    = (const float*)d_in[15];
    float*       out   = (float*)d_out;

    void *p_h1,*p_out1,*p_h2,*p_asrc1,*p_adst1,*p_asrc2,*p_adst2;
    cudaGetSymbolAddress(&p_h1,   g_h1);
    cudaGetSymbolAddress(&p_out1, g_out1);
    cudaGetSymbolAddress(&p_h2,   g_h2);
    cudaGetSymbolAddress(&p_asrc1, g_asrc1);
    cudaGetSymbolAddress(&p_adst1, g_adst1);
    cudaGetSymbolAddress(&p_asrc2, g_asrc2);
    cudaGetSymbolAddress(&p_adst2, g_adst2);

    cudaStream_t s2;
    cudaEvent_t evFork, evJoin;
    cudaStreamCreateWithFlags(&s2, cudaStreamNonBlocking);
    cudaEventCreateWithFlags(&evFork, cudaEventDisableTiming);
    cudaEventCreateWithFlags(&evJoin, cudaEventDisableTiming);

    cudaEventRecord(evFork, 0);

    k_init<<<(Nn+255)/256, 256>>>(We1, ae1, We2, ae2);   // #1
    k_pass1<<<(EPt+255)/256, 256>>>(ea, ei);             // #2
    k_scanA<<<NBLK, 256>>>();                            // #3

    cudaStreamWaitEvent(s2, evFork, 0);
    k_gemm<128,false,float><<<(Nn+63)/64, 256, 0, s2>>>(x, W1, nullptr, as1, ad1,
                        (__half*)p_h1, (float*)p_asrc1, (float*)p_adst1, Nn);  // #4 (ncu target)
    cudaEventRecord(evJoin, s2);

    k_scanB<<<1, 32>>>();                                // #5
    k_scanC<<<NBLK, 256>>>();                            // #6
    k_scatter<<<(EPt+255)/256, 256>>>(ei);               // #7

    cudaStreamWaitEvent(0, evJoin, 0);
    k_layer1<<<(Nn/2*32+255)/256, 256>>>();              // #8

    k_gemm<64,true,__half><<<(Nn+63)/64, 256>>>((const __half*)p_out1, W2, b1, as2, ad2,
                        (__half*)p_h2, (float*)p_asrc2, (float*)p_adst2, Nn);  // #9
    k_layer2<<<(Nn/2*32+255)/256, 256>>>(batch);         // #10

    k_final<<<(Gg*64+255)/256, 256>>>(out, b2);          // #11
}

// round 14
// speedup vs baseline: 1.3920x; 1.0835x over previous
#include <cuda_runtime.h>
#include <cuda_fp16.h>
#include <math.h>

#define Nn   50000
#define Ee   800000
#define EPt  850000   // E + N self loops
#define Gg   64
#define NBLK 49       // ceil(Nn/1024)

// ---------------- scratch ----------------
__device__ __align__(16) __half g_h1  [(size_t)Nn*128];
__device__ __align__(16) __half g_out1[(size_t)Nn*128];
__device__ __align__(16) __half g_h2  [(size_t)Nn*64];
__device__ __align__(16) float  g_asrc1[Nn*4];
__device__ __align__(16) float  g_adst1[Nn*4];
__device__ __align__(16) float  g_asrc2[Nn];
__device__ __align__(16) float  g_adst2[Nn];
__device__ __align__(16) int    g_ssrc [EPt];
__device__ __align__(16) float  g_sae1 [(size_t)EPt*4];
__device__ __align__(16) float  g_sae2 [EPt];
__device__ __align__(16) int    g_deg  [Nn];
__device__ __align__(16) int    g_off  [Nn+1];
__device__ __align__(16) int    g_cur  [Nn];
__device__ __align__(16) int    g_bsum [NBLK];
__device__ __align__(16) int    g_boff [NBLK];
__device__ __align__(16) float  g_sum_ea[16];
__device__ __align__(16) float  g_v1[64];
__device__ __align__(16) float  g_v2[16];
__device__ __align__(16) float  g_lae1[4];
__device__ __align__(16) float  g_lae2[1];
__device__ __align__(16) float  g_pool[Gg*64];
__device__ __align__(16) int    g_cnt [Gg];

__device__ __forceinline__ float lrelu(float x){ return x > 0.f ? x : 0.2f*x; }

// ---------------- 1. init: zero scratch (deg=1 reserves self-loop) + v1/v2 ----------------
__global__ void k_init(const float* __restrict__ We1, const float* __restrict__ ae1,
                       const float* __restrict__ We2, const float* __restrict__ ae2){
    int i = blockIdx.x*blockDim.x + threadIdx.x;
    if(i < Nn){ g_deg[i]=1; g_cur[i]=0; }   // deg starts at 1: slot 0 = self loop
    if(i < 16) g_sum_ea[i]=0.f;
    if(i < Gg*64) g_pool[i]=0.f;
    if(i < Gg) g_cnt[i]=0;
    if(blockIdx.x == 0){
        int t = threadIdx.x;
        if(t < 64){
            int h = t >> 4, d = t & 15;
            float s = 0.f;
            for(int c=0;c<32;c++) s += We1[d*128 + h*32 + c] * ae1[h*32 + c];
            g_v1[h*16 + d] = s;
        }
        if(t < 16){
            float s = 0.f;
            for(int c=0;c<64;c++) s += We2[t*64 + c] * ae2[c];
            g_v2[t] = s;
        }
    }
}

// ---------------- 2. pass0: hist + sum_ea only ----------------
__global__ __launch_bounds__(256) void k_pass0(const float* __restrict__ ea,
                                               const int* __restrict__ ei){
    __shared__ float ssum[16];
    int t = threadIdx.x;
    if(t < 16) ssum[t] = 0.f;
    __syncthreads();
    int e = blockIdx.x*blockDim.x + t;
    float r[16];
#pragma unroll
    for(int i=0;i<16;i++) r[i]=0.f;
    if(e < Ee){
        atomicAdd(&g_deg[__ldg(&ei[Ee + e])], 1);
        const float4* rp = (const float4*)(ea + (size_t)e*16);
        ((float4*)r)[0]=__ldg(rp);   ((float4*)r)[1]=__ldg(rp+1);
        ((float4*)r)[2]=__ldg(rp+2); ((float4*)r)[3]=__ldg(rp+3);
    }
#pragma unroll
    for(int off=16; off; off>>=1)
#pragma unroll
        for(int i=0;i<16;i++) r[i] += __shfl_xor_sync(0xffffffffu, r[i], off);
    if((t & 31)==0)
#pragma unroll
        for(int i=0;i<16;i++) atomicAdd(&ssum[i], r[i]);
    __syncthreads();
    if(t < 16) atomicAdd(&g_sum_ea[t], ssum[t]);
}

// ---------------- 3. scan (3 kernels); lae folded into scanB ----------------
__global__ void k_scanA(){
    __shared__ int wsum[8], wexc[8];
    int t = threadIdx.x, blk = blockIdx.x;
    int base = blk*1024 + t*4;
    int v0 = (base+0<Nn)?g_deg[base+0]:0;
    int v1 = (base+1<Nn)?g_deg[base+1]:0;
    int v2 = (base+2<Nn)?g_deg[base+2]:0;
    int v3 = (base+3<Nn)?g_deg[base+3]:0;
    int s = v0+v1+v2+v3;
    int lane = t&31, w = t>>5;
    int ps = s;
#pragma unroll
    for(int off=1; off<32; off<<=1){
        int n = __shfl_up_sync(0xffffffffu, ps, off);
        if(lane>=off) ps += n;
    }
    if(lane==31) wsum[w] = ps;
    __syncthreads();
    if(t==0){
        int r=0;
#pragma unroll
        for(int k=0;k<8;k++){ wexc[k]=r; r+=wsum[k]; }
        g_bsum[blk]=r;
    }
    __syncthreads();
    int run = wexc[w] + ps - s;
    if(base+0<Nn) g_off[base+0]=run; run+=v0;
    if(base+1<Nn) g_off[base+1]=run; run+=v1;
    if(base+2<Nn) g_off[base+2]=run; run+=v2;
    if(base+3<Nn) g_off[base+3]=run;
}
__global__ void k_scanB(){
    int t = threadIdx.x;
    if(t==0){
        int r=0;
        for(int b=0;b<NBLK;b++){ g_boff[b]=r; r+=g_bsum[b]; }
        g_off[Nn]=EPt;
    }
    if(t>=1 && t<5){
        int h = t-1;
        float s = 0.f;
        for(int d=0;d<16;d++) s += (g_sum_ea[d]*(1.0f/(float)Ee))*g_v1[h*16+d];
        g_lae1[h] = s;
    }
    if(t == 5){
        float s = 0.f;
        for(int d=0;d<16;d++) s += (g_sum_ea[d]*(1.0f/(float)Ee))*g_v2[d];
        g_lae2[0] = s;
    }
}
__global__ void k_scanC(){
    int blk = blockIdx.x;
    if(blk==0) return;
    int add = g_boff[blk];
    int base = blk*1024 + threadIdx.x*4;
#pragma unroll
    for(int j=0;j<4;j++)
        if(base+j < Nn) g_off[base+j] += add;
}

// ---------------- 4. scatter: dots from ea directly; slot 0 reserved per node ----------------
__global__ __launch_bounds__(256) void k_scatter(const int* __restrict__ ei,
                                                 const float* __restrict__ ea){
    __shared__ float sv1[64], sv2[16];
    int t = threadIdx.x;
    if(t < 64) sv1[t] = g_v1[t];
    if(t < 16) sv2[t] = g_v2[t];
    __syncthreads();
    int e = blockIdx.x*blockDim.x + t;
    if(e >= Ee) return;
    int s = __ldg(&ei[e]), d = __ldg(&ei[Ee + e]);
    float r[16];
    const float4* rp = (const float4*)(ea + (size_t)e*16);
    ((float4*)r)[0]=__ldg(rp);   ((float4*)r)[1]=__ldg(rp+1);
    ((float4*)r)[2]=__ldg(rp+2); ((float4*)r)[3]=__ldg(rp+3);
    float ae[4];
#pragma unroll
    for(int h=0;h<4;h++){
        float a=0.f;
#pragma unroll
        for(int i=0;i<16;i++) a += sv1[h*16+i]*r[i];
        ae[h]=a;
    }
    float a2=0.f;
#pragma unroll
    for(int i=0;i<16;i++) a2 += sv2[i]*r[i];
    int pos = g_off[d] + 1 + atomicAdd(&g_cur[d], 1);   // slot 0 = self loop
    g_ssrc[pos] = s;
    *(float4*)&g_sae1[(size_t)pos*4] = make_float4(ae[0],ae[1],ae[2],ae[3]);
    g_sae2[pos] = a2;
}

// ---------------- 5. self-loop fill (slot 0 of each node) ----------------
__global__ void k_selfloop(){
    int d = blockIdx.x*blockDim.x + threadIdx.x;
    if(d >= Nn) return;
    int pos = g_off[d];
    g_ssrc[pos] = d;
    *(float4*)&g_sae1[(size_t)pos*4] = make_float4(g_lae1[0],g_lae1[1],g_lae1[2],g_lae1[3]);
    g_sae2[pos] = g_lae2[0];
}

// ---------------- 6. GEMM: 128xNC block, 8x(NC/16) register tile, fp16 C out ----------------
template<int NC, bool ELU, typename TA>
__global__ __launch_bounds__(256) void k_gemm(const TA* __restrict__ A,
                                              const float* __restrict__ W,
                                              const float* __restrict__ abias,
                                              const float* __restrict__ atts,
                                              const float* __restrict__ attd,
                                              __half* __restrict__ C,
                                              float* __restrict__ oasrc,
                                              float* __restrict__ oadst, int M){
    constexpr int CPT = NC/16;                 // cols per thread (8 or 4)
    constexpr int AST = 132;                   // transposed-A stride (mult of 4)
    __shared__ float AsT[32*AST];              // [kk][row 0..127]
    __shared__ float Ws[32*NC];
    __shared__ float as_s[NC], ad_s[NC];
    const int t  = threadIdx.x;
    const int tr = t >> 4, tc = t & 15;
    const int r0 = blockIdx.x * 128;
    if(t < NC){ as_s[t]=__ldg(&atts[t]); ad_s[t]=__ldg(&attd[t]); }
    float acc[8][CPT];
#pragma unroll
    for(int i=0;i<8;i++)
#pragma unroll
        for(int j=0;j<CPT;j++) acc[i][j]=0.f;

    for(int kc=0; kc<128; kc+=32){
        // stage A chunk 128x32 transposed
        if constexpr (!ELU){
#pragma unroll
            for(int i=0;i<4;i++){
                int idx = t + i*256; int r = idx>>3; int c4 = idx&7;
                float4 v = make_float4(0.f,0.f,0.f,0.f);
                if(r0 + r < M) v = __ldg((const float4*)&((const float*)A)[(size_t)(r0+r)*128 + kc + c4*4]);
                AsT[(c4*4+0)*AST + r] = v.x;
                AsT[(c4*4+1)*AST + r] = v.y;
                AsT[(c4*4+2)*AST + r] = v.z;
                AsT[(c4*4+3)*AST + r] = v.w;
            }
        } else {
#pragma unroll
            for(int i=0;i<2;i++){
                int idx = t + i*256; int r = idx>>2; int c8 = (idx&3)*8;
                float f[8] = {0,0,0,0,0,0,0,0};
                if(r0 + r < M){
                    uint4 u = __ldg((const uint4*)&((const __half*)A)[(size_t)(r0+r)*128 + kc + c8]);
                    float2 a0=__half22float2(*(__half2*)&u.x), a1=__half22float2(*(__half2*)&u.y);
                    float2 a2=__half22float2(*(__half2*)&u.z), a3=__half22float2(*(__half2*)&u.w);
                    f[0]=a0.x; f[1]=a0.y; f[2]=a1.x; f[3]=a1.y;
                    f[4]=a2.x; f[5]=a2.y; f[6]=a3.x; f[7]=a3.y;
                    float4 b0 = __ldg((const float4*)&abias[kc+c8]);
                    float4 b1 = __ldg((const float4*)&abias[kc+c8+4]);
                    f[0]+=b0.x; f[1]+=b0.y; f[2]+=b0.z; f[3]+=b0.w;
                    f[4]+=b1.x; f[5]+=b1.y; f[6]+=b1.z; f[7]+=b1.w;
#pragma unroll
                    for(int j=0;j<8;j++) f[j] = f[j]>0.f ? f[j] : expm1f(f[j]);
                }
#pragma unroll
                for(int j=0;j<8;j++) AsT[(c8+j)*AST + r] = f[j];
            }
        }
        // stage W chunk 32xNC
#pragma unroll
        for(int f=t; f < 32*NC/4; f += 256){
            int k = f/(NC/4); int c = f%(NC/4);
            *(float4*)&Ws[k*NC + c*4] = __ldg((const float4*)&W[(size_t)(kc+k)*NC + c*4]);
        }
        __syncthreads();
#pragma unroll 4
        for(int kk=0; kk<32; kk++){
            float4 a0 = *(const float4*)&AsT[kk*AST + tr*8];
            float4 a1 = *(const float4*)&AsT[kk*AST + tr*8 + 4];
            float av[8] = {a0.x,a0.y,a0.z,a0.w,a1.x,a1.y,a1.z,a1.w};
            float4 b0 = *(const float4*)&Ws[kk*NC + tc*CPT];
#pragma unroll
            for(int i=0;i<8;i++){
                acc[i][0]+=av[i]*b0.x; acc[i][1]+=av[i]*b0.y;
                acc[i][2]+=av[i]*b0.z; acc[i][3]+=av[i]*b0.w;
            }
            if constexpr (CPT == 8){
                float4 b1 = *(const float4*)&Ws[kk*NC + tc*CPT + 4];
#pragma unroll
                for(int i=0;i<8;i++){
                    acc[i][4]+=av[i]*b1.x; acc[i][5]+=av[i]*b1.y;
                    acc[i][6]+=av[i]*b1.z; acc[i][7]+=av[i]*b1.w;
                }
            }
        }
        __syncthreads();
    }
#pragma unroll
    for(int i=0;i<8;i++){
        int row = r0 + tr*8 + i;
        float ps=0.f, pd=0.f;
#pragma unroll
        for(int j=0;j<CPT;j++){
            float a = acc[i][j];
            ps += a*as_s[tc*CPT+j]; pd += a*ad_s[tc*CPT+j];
        }
        if constexpr (NC == 128){
            ps += __shfl_xor_sync(0xffffffffu, ps, 1); pd += __shfl_xor_sync(0xffffffffu, pd, 1);
            ps += __shfl_xor_sync(0xffffffffu, ps, 2); pd += __shfl_xor_sync(0xffffffffu, pd, 2);
            if((tc&3)==0 && row<M){ oasrc[row*4+(tc>>2)]=ps; oadst[row*4+(tc>>2)]=pd; }
        } else {
            ps += __shfl_xor_sync(0xffffffffu, ps, 1); pd += __shfl_xor_sync(0xffffffffu, pd, 1);
            ps += __shfl_xor_sync(0xffffffffu, ps, 2); pd += __shfl_xor_sync(0xffffffffu, pd, 2);
            ps += __shfl_xor_sync(0xffffffffu, ps, 4); pd += __shfl_xor_sync(0xffffffffu, pd, 4);
            ps += __shfl_xor_sync(0xffffffffu, ps, 8); pd += __shfl_xor_sync(0xffffffffu, pd, 8);
            if(tc==0 && row<M){ oasrc[row]=ps; oadst[row]=pd; }
        }
        if(row < M){
            __half2 hh[CPT/2];
#pragma unroll
            for(int j=0;j<CPT/2;j++)
                hh[j] = __float22half2_rn(make_float2(acc[i][2*j], acc[i][2*j+1]));
            if constexpr (CPT == 8)
                *(uint4*)&C[(size_t)row*NC + tc*CPT] = *(uint4*)hh;
            else
                *(uint2*)&C[(size_t)row*NC + tc*CPT] = *(uint2*)hh;
        }
    }
}

// ---------------- 7. fused layer-1: 2 nodes/warp ----------------
#define COMB8(a, u) { \
    float2 fa=__half22float2(*(__half2*)&(u).x), fb=__half22float2(*(__half2*)&(u).y); \
    float2 fc=__half22float2(*(__half2*)&(u).z), fd=__half22float2(*(__half2*)&(u).w); \
    if((a) <= m){ float w_=__expf((a)-m); sden+=w_; \
        acc[0]+=fa.x*w_; acc[1]+=fa.y*w_; acc[2]+=fb.x*w_; acc[3]+=fb.y*w_; \
        acc[4]+=fc.x*w_; acc[5]+=fc.y*w_; acc[6]+=fd.x*w_; acc[7]+=fd.y*w_; } \
    else { float sc=__expf(m-(a)); sden=sden*sc+1.f; \
        acc[0]=acc[0]*sc+fa.x; acc[1]=acc[1]*sc+fa.y; acc[2]=acc[2]*sc+fb.x; acc[3]=acc[3]*sc+fb.y; \
        acc[4]=acc[4]*sc+fc.x; acc[5]=acc[5]*sc+fc.y; acc[6]=acc[6]*sc+fd.x; acc[7]=acc[7]*sc+fd.y; m=(a);} }

__global__ __launch_bounds__(256) void k_layer1(){
    int lane = threadIdx.x & 31;
    int warp = (blockIdx.x*blockDim.x + threadIdx.x) >> 5;
    int side = lane >> 4, sl = lane & 15;
    int d = warp*2 + side;
    if(d >= Nn) return;
    int beg = g_off[d], end = g_off[d+1];
    int h = sl >> 2;
    float adst = __ldg(&g_adst1[d*4+h]);
    float m = -1e30f, sden = 0.f;
    float acc[8] = {0.f,0.f,0.f,0.f,0.f,0.f,0.f,0.f};
    int i = beg;
    for(; i+4 <= end; i+=4){
        int s0=__ldg(&g_ssrc[i+0]), s1=__ldg(&g_ssrc[i+1]),
            s2=__ldg(&g_ssrc[i+2]), s3=__ldg(&g_ssrc[i+3]);
        float e0=__ldg(&g_sae1[(size_t)(i+0)*4+h]), e1=__ldg(&g_sae1[(size_t)(i+1)*4+h]),
              e2=__ldg(&g_sae1[(size_t)(i+2)*4+h]), e3=__ldg(&g_sae1[(size_t)(i+3)*4+h]);
        float a0=lrelu(__ldg(&g_asrc1[s0*4+h])+adst+e0);
        float a1=lrelu(__ldg(&g_asrc1[s1*4+h])+adst+e1);
        float a2=lrelu(__ldg(&g_asrc1[s2*4+h])+adst+e2);
        float a3=lrelu(__ldg(&g_asrc1[s3*4+h])+adst+e3);
        uint4 v0=__ldg((const uint4*)&g_h1[(size_t)s0*128+sl*8]);
        uint4 v1=__ldg((const uint4*)&g_h1[(size_t)s1*128+sl*8]);
        uint4 v2=__ldg((const uint4*)&g_h1[(size_t)s2*128+sl*8]);
        uint4 v3=__ldg((const uint4*)&g_h1[(size_t)s3*128+sl*8]);
        COMB8(a0,v0); COMB8(a1,v1); COMB8(a2,v2); COMB8(a3,v3);
    }
    for(; i<end; i++){
        int s = __ldg(&g_ssrc[i]);
        float a = lrelu(__ldg(&g_asrc1[s*4+h])+adst+__ldg(&g_sae1[(size_t)i*4+h]));
        uint4 hv = __ldg((const uint4*)&g_h1[(size_t)s*128+sl*8]);
        COMB8(a,hv);
    }
    float inv = 1.f/sden;
    __half2 o[4];
#pragma unroll
    for(int j=0;j<4;j++)
        o[j] = __float22half2_rn(make_float2(acc[2*j]*inv, acc[2*j+1]*inv));
    *(uint4*)&g_out1[(size_t)d*128 + sl*8] = *(uint4*)o;
}

// ---------------- 8. fused layer-2 + pool: 2 nodes/warp ----------------
#define COMB4(a, u) { \
    float2 fa=__half22float2(*(__half2*)&(u).x), fb=__half22float2(*(__half2*)&(u).y); \
    if((a) <= m){ float w_=__expf((a)-m); sden+=w_; \
        acc[0]+=fa.x*w_; acc[1]+=fa.y*w_; acc[2]+=fb.x*w_; acc[3]+=fb.y*w_; } \
    else { float sc=__expf(m-(a)); sden=sden*sc+1.f; \
        acc[0]=acc[0]*sc+fa.x; acc[1]=acc[1]*sc+fa.y; acc[2]=acc[2]*sc+fb.x; acc[3]=acc[3]*sc+fb.y; m=(a);} }

__global__ __launch_bounds__(256) void k_layer2(const int* __restrict__ batch){
    int lane = threadIdx.x & 31;
    int warp = (blockIdx.x*blockDim.x + threadIdx.x) >> 5;
    int side = lane >> 4, sl = lane & 15;
    int d = warp*2 + side;
    if(d >= Nn) return;
    int beg = g_off[d], end = g_off[d+1];
    float adst = __ldg(&g_adst2[d]);
    float m = -1e30f, sden = 0.f;
    float acc[4] = {0.f,0.f,0.f,0.f};
    int i = beg;
    for(; i+4 <= end; i+=4){
        int s0=__ldg(&g_ssrc[i+0]), s1=__ldg(&g_ssrc[i+1]),
            s2=__ldg(&g_ssrc[i+2]), s3=__ldg(&g_ssrc[i+3]);
        float a0=lrelu(__ldg(&g_asrc2[s0])+adst+__ldg(&g_sae2[i+0]));
        float a1=lrelu(__ldg(&g_asrc2[s1])+adst+__ldg(&g_sae2[i+1]));
        float a2=lrelu(__ldg(&g_asrc2[s2])+adst+__ldg(&g_sae2[i+2]));
        float a3=lrelu(__ldg(&g_asrc2[s3])+adst+__ldg(&g_sae2[i+3]));
        uint2 v0=__ldg((const uint2*)&g_h2[(size_t)s0*64+sl*4]);
        uint2 v1=__ldg((const uint2*)&g_h2[(size_t)s1*64+sl*4]);
        uint2 v2=__ldg((const uint2*)&g_h2[(size_t)s2*64+sl*4]);
        uint2 v3=__ldg((const uint2*)&g_h2[(size_t)s3*64+sl*4]);
        COMB4(a0,v0); COMB4(a1,v1); COMB4(a2,v2); COMB4(a3,v3);
    }
    for(; i<end; i++){
        int s = __ldg(&g_ssrc[i]);
        float a = lrelu(__ldg(&g_asrc2[s])+adst+__ldg(&g_sae2[i]));
        uint2 hv = __ldg((const uint2*)&g_h2[(size_t)s*64+sl*4]);
        COMB4(a,hv);
    }
    float inv = 1.f/sden;
    int g = __ldg(&batch[d]);
    atomicAdd((float4*)&g_pool[g*64 + sl*4],
              make_float4(acc[0]*inv, acc[1]*inv, acc[2]*inv, acc[3]*inv));
    if(sl==0) atomicAdd(&g_cnt[g], 1);
}

// ---------------- 9. final ----------------
__global__ void k_final(float* __restrict__ out, const float* __restrict__ b2){
    int i = blockIdx.x*blockDim.x + threadIdx.x;
    if(i >= Gg*64) return;
    out[i] = g_pool[i] / fmaxf((float)g_cnt[i >> 6], 1.0f) + __ldg(&b2[i & 63]);
}

// ---------------- host launcher ----------------
extern "C" void kernel_launch(void* const* d_in, const int* in_sizes, int n_in,
                              void* d_out, int out_size){
    (void)in_sizes; (void)n_in; (void)out_size;
    const float* x     = (const float*)d_in[0];
    const int*   ei    = (const int*)d_in[1];
    const float* ea    = (const float*)d_in[2];
    const int*   batch = (const int*)d_in[3];
    const float* W1    = (const float*)d_in[4];
    const float* as1   = (const float*)d_in[5];
    const float* ad1   = (const float*)d_in[6];
    const float* We1   = (const float*)d_in[7];
    const float* ae1   = (const float*)d_in[8];
    const float* b1    = (const float*)d_in[9];
    const float* W2    = (const float*)d_in[10];
    const float* as2   = (const float*)d_in[11];
    const float* ad2   = (const float*)d_in[12];
    const float* We2   = (const float*)d_in[13];
    const float* ae2   = (const float*)d_in[14];
    const float* b2    = (const float*)d_in[15];
    float*       out   = (float*)d_out;

    void *p_h1,*p_out1,*p_h2,*p_asrc1,*p_adst1,*p_asrc2,*p_adst2;
    cudaGetSymbolAddress(&p_h1,   g_h1);
    cudaGetSymbolAddress(&p_out1, g_out1);
    cudaGetSymbolAddress(&p_h2,   g_h2);
    cudaGetSymbolAddress(&p_asrc1, g_asrc1);
    cudaGetSymbolAddress(&p_adst1, g_adst1);
    cudaGetSymbolAddress(&p_asrc2, g_asrc2);
    cudaGetSymbolAddress(&p_adst2, g_adst2);

    cudaStream_t s2;
    cudaEvent_t evFork, evJoin;
    cudaStreamCreateWithFlags(&s2, cudaStreamNonBlocking);
    cudaEventCreateWithFlags(&evFork, cudaEventDisableTiming);
    cudaEventCreateWithFlags(&evJoin, cudaEventDisableTiming);

    cudaEventRecord(evFork, 0);

    k_init<<<(Nn+255)/256, 256>>>(We1, ae1, We2, ae2);   // #1
    k_pass0<<<(Ee+255)/256, 256>>>(ea, ei);              // #2
    k_scanA<<<NBLK, 256>>>();                            // #3

    cudaStreamWaitEvent(s2, evFork, 0);
    k_gemm<128,false,float><<<(Nn+127)/128, 256, 0, s2>>>(x, W1, nullptr, as1, ad1,
                        (__half*)p_h1, (float*)p_asrc1, (float*)p_adst1, Nn);  // #4 (ncu target)
    cudaEventRecord(evJoin, s2);

    k_scanB<<<1, 32>>>();                                // #5
    k_scanC<<<NBLK, 256>>>();                            // #6
    k_scatter<<<(Ee+255)/256, 256>>>(ei, ea);            // #7
    k_selfloop<<<(Nn+255)/256, 256>>>();                 // #8

    cudaStreamWaitEvent(0, evJoin, 0);
    k_layer1<<<(Nn/2*32+255)/256, 256>>>();              // #9

    k_gemm<64,true,__half><<<(Nn+127)/128, 256>>>((const __half*)p_out1, W2, b1, as2, ad2,
                        (__half*)p_h2, (float*)p_asrc2, (float*)p_adst2, Nn);  // #10
    k_layer2<<<(Nn/2*32+255)/256, 256>>>(batch);         // #11

    k_final<<<(Gg*64+255)/256, 256>>>(out, b2);          // #12
}

// round 15
// speedup vs baseline: 1.4614x; 1.0499x over previous
#include <cuda_runtime.h>
#include <cuda_fp16.h>
#include <math.h>

#define Nn   50000
#define Ee   800000
#define EPt  850000   // E + N self loops
#define Gg   64
#define NBLK 49       // ceil(Nn/1024)

// ---------------- scratch ----------------
__device__ __align__(16) __half g_h1  [(size_t)Nn*128];
__device__ __align__(16) __half g_out1[(size_t)Nn*128];
__device__ __align__(16) __half g_h2  [(size_t)Nn*64];
__device__ __align__(16) float  g_asrc1[Nn*4];
__device__ __align__(16) float  g_adst1[Nn*4];
__device__ __align__(16) float  g_asrc2[Nn];
__device__ __align__(16) float  g_adst2[Nn];
__device__ __align__(16) int    g_ssrc [EPt];
__device__ __align__(16) float  g_sae1 [(size_t)EPt*4];
__device__ __align__(16) float  g_sae2 [EPt];
__device__ __align__(16) int    g_deg  [Nn];
__device__ __align__(16) int    g_off  [Nn+1];
__device__ __align__(16) int    g_cur  [Nn];
__device__ __align__(16) int    g_bsum [NBLK];
__device__ __align__(16) int    g_boff [NBLK];
__device__ __align__(16) float  g_sum_ea[16];
__device__ __align__(16) float  g_v1[64];
__device__ __align__(16) float  g_v2[16];
__device__ __align__(16) float  g_pool[Gg*64];
__device__ __align__(16) int    g_cnt [Gg];

__device__ __forceinline__ float lrelu(float x){ return x > 0.f ? x : 0.2f*x; }

// ---------------- 1. init: zero scratch (deg=1 reserves self-loop) + v1/v2 ----------------
__global__ void k_init(const float* __restrict__ We1, const float* __restrict__ ae1,
                       const float* __restrict__ We2, const float* __restrict__ ae2){
    int i = blockIdx.x*blockDim.x + threadIdx.x;
    if(i < Nn){ g_deg[i]=1; g_cur[i]=0; }
    if(i < 16) g_sum_ea[i]=0.f;
    if(i < Gg*64) g_pool[i]=0.f;
    if(i < Gg) g_cnt[i]=0;
    if(blockIdx.x == 0){
        int t = threadIdx.x;
        if(t < 64){
            int h = t >> 4, d = t & 15;
            float s = 0.f;
            for(int c=0;c<32;c++) s += We1[d*128 + h*32 + c] * ae1[h*32 + c];
            g_v1[h*16 + d] = s;
        }
        if(t < 16){
            float s = 0.f;
            for(int c=0;c<64;c++) s += We2[t*64 + c] * ae2[c];
            g_v2[t] = s;
        }
    }
}

// ---------------- 2. hist only ----------------
__global__ void k_hist(const int* __restrict__ ei){
    int e = blockIdx.x*blockDim.x + threadIdx.x;
    if(e < Ee) atomicAdd(&g_deg[__ldg(&ei[Ee + e])], 1);
}

// ---------------- 3. scan (3 kernels) ----------------
__global__ void k_scanA(){
    __shared__ int wsum[8], wexc[8];
    int t = threadIdx.x, blk = blockIdx.x;
    int base = blk*1024 + t*4;
    int v0 = (base+0<Nn)?g_deg[base+0]:0;
    int v1 = (base+1<Nn)?g_deg[base+1]:0;
    int v2 = (base+2<Nn)?g_deg[base+2]:0;
    int v3 = (base+3<Nn)?g_deg[base+3]:0;
    int s = v0+v1+v2+v3;
    int lane = t&31, w = t>>5;
    int ps = s;
#pragma unroll
    for(int off=1; off<32; off<<=1){
        int n = __shfl_up_sync(0xffffffffu, ps, off);
        if(lane>=off) ps += n;
    }
    if(lane==31) wsum[w] = ps;
    __syncthreads();
    if(t==0){
        int r=0;
#pragma unroll
        for(int k=0;k<8;k++){ wexc[k]=r; r+=wsum[k]; }
        g_bsum[blk]=r;
    }
    __syncthreads();
    int run = wexc[w] + ps - s;
    if(base+0<Nn) g_off[base+0]=run; run+=v0;
    if(base+1<Nn) g_off[base+1]=run; run+=v1;
    if(base+2<Nn) g_off[base+2]=run; run+=v2;
    if(base+3<Nn) g_off[base+3]=run;
}
__global__ void k_scanB(){
    if(threadIdx.x==0){
        int r=0;
        for(int b=0;b<NBLK;b++){ g_boff[b]=r; r+=g_bsum[b]; }
        g_off[Nn]=EPt;
    }
}
__global__ void k_scanC(){
    int blk = blockIdx.x;
    if(blk==0) return;
    int add = g_boff[blk];
    int base = blk*1024 + threadIdx.x*4;
#pragma unroll
    for(int j=0;j<4;j++)
        if(base+j < Nn) g_off[base+j] += add;
}

// ---------------- 4. scatter: dots from ea + sum_ea accumulation; slot 0 reserved ----------------
__global__ __launch_bounds__(256) void k_scatter(const int* __restrict__ ei,
                                                 const float* __restrict__ ea){
    __shared__ float sv1[64], sv2[16], ssum[16];
    int t = threadIdx.x;
    if(t < 64) sv1[t] = g_v1[t];
    if(t < 16){ sv2[t] = g_v2[t]; ssum[t] = 0.f; }
    __syncthreads();
    int e = blockIdx.x*blockDim.x + t;
    float r[16];
#pragma unroll
    for(int i=0;i<16;i++) r[i]=0.f;
    if(e < Ee){
        int s = __ldg(&ei[e]), d = __ldg(&ei[Ee + e]);
        const float4* rp = (const float4*)(ea + (size_t)e*16);
        ((float4*)r)[0]=__ldg(rp);   ((float4*)r)[1]=__ldg(rp+1);
        ((float4*)r)[2]=__ldg(rp+2); ((float4*)r)[3]=__ldg(rp+3);
        float ae[4];
#pragma unroll
        for(int h=0;h<4;h++){
            float a=0.f;
#pragma unroll
            for(int i=0;i<16;i++) a += sv1[h*16+i]*r[i];
            ae[h]=a;
        }
        float a2=0.f;
#pragma unroll
        for(int i=0;i<16;i++) a2 += sv2[i]*r[i];
        int pos = g_off[d] + 1 + atomicAdd(&g_cur[d], 1);
        g_ssrc[pos] = s;
        *(float4*)&g_sae1[(size_t)pos*4] = make_float4(ae[0],ae[1],ae[2],ae[3]);
        g_sae2[pos] = a2;
    }
    // sum_ea reduction (rows already in registers)
#pragma unroll
    for(int off=16; off; off>>=1)
#pragma unroll
        for(int i=0;i<16;i++) r[i] += __shfl_xor_sync(0xffffffffu, r[i], off);
    if((t & 31)==0)
#pragma unroll
        for(int i=0;i<16;i++) atomicAdd(&ssum[i], r[i]);
    __syncthreads();
    if(t < 16) atomicAdd(&g_sum_ea[t], ssum[t]);
}

// ---------------- 5. self-loop fill (slot 0) with per-block lae compute ----------------
__global__ void k_selfloop(){
    __shared__ float slae1[4];
    __shared__ float slae2;
    int t = threadIdx.x;
    if(t < 4){
        float s = 0.f;
        for(int d=0;d<16;d++) s += (g_sum_ea[d]*(1.0f/(float)Ee))*g_v1[t*16+d];
        slae1[t] = s;
    }
    if(t == 4){
        float s = 0.f;
        for(int d=0;d<16;d++) s += (g_sum_ea[d]*(1.0f/(float)Ee))*g_v2[d];
        slae2 = s;
    }
    __syncthreads();
    int d = blockIdx.x*blockDim.x + t;
    if(d >= Nn) return;
    int pos = g_off[d];
    g_ssrc[pos] = d;
    *(float4*)&g_sae1[(size_t)pos*4] = make_float4(slae1[0],slae1[1],slae1[2],slae1[3]);
    g_sae2[pos] = slae2;
}

// ---------------- 6. GEMM: 64xNC block, 128 threads, 8x(NC/16) register tile ----------------
template<int NC, bool ELU, typename TA>
__global__ __launch_bounds__(128) void k_gemm(const TA* __restrict__ A,
                                              const float* __restrict__ W,
                                              const float* __restrict__ abias,
                                              const float* __restrict__ atts,
                                              const float* __restrict__ attd,
                                              __half* __restrict__ C,
                                              float* __restrict__ oasrc,
                                              float* __restrict__ oadst, int M){
    constexpr int CPT = NC/16;                 // cols per thread (8 or 4)
    constexpr int AST = 68;                    // transposed-A stride
    __shared__ float AsT[32*AST];              // [kk][row 0..63]
    __shared__ float Ws[32*NC];
    __shared__ float as_s[NC], ad_s[NC];
    const int t  = threadIdx.x;
    const int tr = t >> 4, tc = t & 15;
    const int r0 = blockIdx.x * 64;
    if(t < NC){ as_s[t]=__ldg(&atts[t]); ad_s[t]=__ldg(&attd[t]); }
    float acc[8][CPT];
#pragma unroll
    for(int i=0;i<8;i++)
#pragma unroll
        for(int j=0;j<CPT;j++) acc[i][j]=0.f;

    for(int kc=0; kc<128; kc+=32){
        // stage A chunk 64x32 transposed
        if constexpr (!ELU){
#pragma unroll
            for(int i=0;i<4;i++){
                int idx = t + i*128; int r = idx>>3; int c4 = idx&7;
                float4 v = make_float4(0.f,0.f,0.f,0.f);
                if(r0 + r < M) v = __ldg((const float4*)&((const float*)A)[(size_t)(r0+r)*128 + kc + c4*4]);
                AsT[(c4*4+0)*AST + r] = v.x;
                AsT[(c4*4+1)*AST + r] = v.y;
                AsT[(c4*4+2)*AST + r] = v.z;
                AsT[(c4*4+3)*AST + r] = v.w;
            }
        } else {
#pragma unroll
            for(int i=0;i<2;i++){
                int idx = t + i*128; int r = idx>>2; int c8 = (idx&3)*8;
                float f[8] = {0,0,0,0,0,0,0,0};
                if(r0 + r < M){
                    uint4 u = __ldg((const uint4*)&((const __half*)A)[(size_t)(r0+r)*128 + kc + c8]);
                    float2 a0=__half22float2(*(__half2*)&u.x), a1=__half22float2(*(__half2*)&u.y);
                    float2 a2=__half22float2(*(__half2*)&u.z), a3=__half22float2(*(__half2*)&u.w);
                    f[0]=a0.x; f[1]=a0.y; f[2]=a1.x; f[3]=a1.y;
                    f[4]=a2.x; f[5]=a2.y; f[6]=a3.x; f[7]=a3.y;
                    float4 b0 = __ldg((const float4*)&abias[kc+c8]);
                    float4 b1 = __ldg((const float4*)&abias[kc+c8+4]);
                    f[0]+=b0.x; f[1]+=b0.y; f[2]+=b0.z; f[3]+=b0.w;
                    f[4]+=b1.x; f[5]+=b1.y; f[6]+=b1.z; f[7]+=b1.w;
#pragma unroll
                    for(int j=0;j<8;j++) f[j] = f[j]>0.f ? f[j] : expm1f(f[j]);
                }
#pragma unroll
                for(int j=0;j<8;j++) AsT[(c8+j)*AST + r] = f[j];
            }
        }
        // stage W chunk 32xNC
#pragma unroll
        for(int f=t; f < 32*NC/4; f += 128){
            int k = f/(NC/4); int c = f%(NC/4);
            *(float4*)&Ws[k*NC + c*4] = __ldg((const float4*)&W[(size_t)(kc+k)*NC + c*4]);
        }
        __syncthreads();
#pragma unroll 4
        for(int kk=0; kk<32; kk++){
            float4 a0 = *(const float4*)&AsT[kk*AST + tr*8];
            float4 a1 = *(const float4*)&AsT[kk*AST + tr*8 + 4];
            float av[8] = {a0.x,a0.y,a0.z,a0.w,a1.x,a1.y,a1.z,a1.w};
            float4 b0 = *(const float4*)&Ws[kk*NC + tc*CPT];
#pragma unroll
            for(int i=0;i<8;i++){
                acc[i][0]+=av[i]*b0.x; acc[i][1]+=av[i]*b0.y;
                acc[i][2]+=av[i]*b0.z; acc[i][3]+=av[i]*b0.w;
            }
            if constexpr (CPT == 8){
                float4 b1 = *(const float4*)&Ws[kk*NC + tc*CPT + 4];
#pragma unroll
                for(int i=0;i<8;i++){
                    acc[i][4]+=av[i]*b1.x; acc[i][5]+=av[i]*b1.y;
                    acc[i][6]+=av[i]*b1.z; acc[i][7]+=av[i]*b1.w;
                }
            }
        }
        __syncthreads();
    }
#pragma unroll
    for(int i=0;i<8;i++){
        int row = r0 + tr*8 + i;
        float ps=0.f, pd=0.f;
#pragma unroll
        for(int j=0;j<CPT;j++){
            float a = acc[i][j];
            ps += a*as_s[tc*CPT+j]; pd += a*ad_s[tc*CPT+j];
        }
        if constexpr (NC == 128){
            ps += __shfl_xor_sync(0xffffffffu, ps, 1); pd += __shfl_xor_sync(0xffffffffu, pd, 1);
            ps += __shfl_xor_sync(0xffffffffu, ps, 2); pd += __shfl_xor_sync(0xffffffffu, pd, 2);
            if((tc&3)==0 && row<M){ oasrc[row*4+(tc>>2)]=ps; oadst[row*4+(tc>>2)]=pd; }
        } else {
            ps += __shfl_xor_sync(0xffffffffu, ps, 1); pd += __shfl_xor_sync(0xffffffffu, pd, 1);
            ps += __shfl_xor_sync(0xffffffffu, ps, 2); pd += __shfl_xor_sync(0xffffffffu, pd, 2);
            ps += __shfl_xor_sync(0xffffffffu, ps, 4); pd += __shfl_xor_sync(0xffffffffu, pd, 4);
            ps += __shfl_xor_sync(0xffffffffu, ps, 8); pd += __shfl_xor_sync(0xffffffffu, pd, 8);
            if(tc==0 && row<M){ oasrc[row]=ps; oadst[row]=pd; }
        }
        if(row < M){
            __half2 hh[CPT/2];
#pragma unroll
            for(int j=0;j<CPT/2;j++)
                hh[j] = __float22half2_rn(make_float2(acc[i][2*j], acc[i][2*j+1]));
            if constexpr (CPT == 8)
                *(uint4*)&C[(size_t)row*NC + tc*CPT] = *(uint4*)hh;
            else
                *(uint2*)&C[(size_t)row*NC + tc*CPT] = *(uint2*)hh;
        }
    }
}

// ---------------- 7. fused layer-1: 2 nodes/warp ----------------
#define COMB8(a, u) { \
    float2 fa=__half22float2(*(__half2*)&(u).x), fb=__half22float2(*(__half2*)&(u).y); \
    float2 fc=__half22float2(*(__half2*)&(u).z), fd=__half22float2(*(__half2*)&(u).w); \
    if((a) <= m){ float w_=__expf((a)-m); sden+=w_; \
        acc[0]+=fa.x*w_; acc[1]+=fa.y*w_; acc[2]+=fb.x*w_; acc[3]+=fb.y*w_; \
        acc[4]+=fc.x*w_; acc[5]+=fc.y*w_; acc[6]+=fd.x*w_; acc[7]+=fd.y*w_; } \
    else { float sc=__expf(m-(a)); sden=sden*sc+1.f; \
        acc[0]=acc[0]*sc+fa.x; acc[1]=acc[1]*sc+fa.y; acc[2]=acc[2]*sc+fb.x; acc[3]=acc[3]*sc+fb.y; \
        acc[4]=acc[4]*sc+fc.x; acc[5]=acc[5]*sc+fc.y; acc[6]=acc[6]*sc+fd.x; acc[7]=acc[7]*sc+fd.y; m=(a);} }

__global__ __launch_bounds__(256) void k_layer1(){
    int lane = threadIdx.x & 31;
    int warp = (blockIdx.x*blockDim.x + threadIdx.x) >> 5;
    int side = lane >> 4, sl = lane & 15;
    int d = warp*2 + side;
    if(d >= Nn) return;
    int beg = g_off[d], end = g_off[d+1];
    int h = sl >> 2;
    float adst = __ldg(&g_adst1[d*4+h]);
    float m = -1e30f, sden = 0.f;
    float acc[8] = {0.f,0.f,0.f,0.f,0.f,0.f,0.f,0.f};
    int i = beg;
    for(; i+4 <= end; i+=4){
        int s0=__ldg(&g_ssrc[i+0]), s1=__ldg(&g_ssrc[i+1]),
            s2=__ldg(&g_ssrc[i+2]), s3=__ldg(&g_ssrc[i+3]);
        float e0=__ldg(&g_sae1[(size_t)(i+0)*4+h]), e1=__ldg(&g_sae1[(size_t)(i+1)*4+h]),
              e2=__ldg(&g_sae1[(size_t)(i+2)*4+h]), e3=__ldg(&g_sae1[(size_t)(i+3)*4+h]);
        float a0=lrelu(__ldg(&g_asrc1[s0*4+h])+adst+e0);
        float a1=lrelu(__ldg(&g_asrc1[s1*4+h])+adst+e1);
        float a2=lrelu(__ldg(&g_asrc1[s2*4+h])+adst+e2);
        float a3=lrelu(__ldg(&g_asrc1[s3*4+h])+adst+e3);
        uint4 v0=__ldg((const uint4*)&g_h1[(size_t)s0*128+sl*8]);
        uint4 v1=__ldg((const uint4*)&g_h1[(size_t)s1*128+sl*8]);
        uint4 v2=__ldg((const uint4*)&g_h1[(size_t)s2*128+sl*8]);
        uint4 v3=__ldg((const uint4*)&g_h1[(size_t)s3*128+sl*8]);
        COMB8(a0,v0); COMB8(a1,v1); COMB8(a2,v2); COMB8(a3,v3);
    }
    for(; i<end; i++){
        int s = __ldg(&g_ssrc[i]);
        float a = lrelu(__ldg(&g_asrc1[s*4+h])+adst+__ldg(&g_sae1[(size_t)i*4+h]));
        uint4 hv = __ldg((const uint4*)&g_h1[(size_t)s*128+sl*8]);
        COMB8(a,hv);
    }
    float inv = 1.f/sden;
    __half2 o[4];
#pragma unroll
    for(int j=0;j<4;j++)
        o[j] = __float22half2_rn(make_float2(acc[2*j]*inv, acc[2*j+1]*inv));
    *(uint4*)&g_out1[(size_t)d*128 + sl*8] = *(uint4*)o;
}

// ---------------- 8. fused layer-2 + pool: 2 nodes/warp ----------------
#define COMB4(a, u) { \
    float2 fa=__half22float2(*(__half2*)&(u).x), fb=__half22float2(*(__half2*)&(u).y); \
    if((a) <= m){ float w_=__expf((a)-m); sden+=w_; \
        acc[0]+=fa.x*w_; acc[1]+=fa.y*w_; acc[2]+=fb.x*w_; acc[3]+=fb.y*w_; } \
    else { float sc=__expf(m-(a)); sden=sden*sc+1.f; \
        acc[0]=acc[0]*sc+fa.x; acc[1]=acc[1]*sc+fa.y; acc[2]=acc[2]*sc+fb.x; acc[3]=acc[3]*sc+fb.y; m=(a);} }

__global__ __launch_bounds__(256) void k_layer2(const int* __restrict__ batch){
    int lane = threadIdx.x & 31;
    int warp = (blockIdx.x*blockDim.x + threadIdx.x) >> 5;
    int side = lane >> 4, sl = lane & 15;
    int d = warp*2 + side;
    if(d >= Nn) return;
    int beg = g_off[d], end = g_off[d+1];
    float adst = __ldg(&g_adst2[d]);
    float m = -1e30f, sden = 0.f;
    float acc[4] = {0.f,0.f,0.f,0.f};
    int i = beg;
    for(; i+4 <= end; i+=4){
        int s0=__ldg(&g_ssrc[i+0]), s1=__ldg(&g_ssrc[i+1]),
            s2=__ldg(&g_ssrc[i+2]), s3=__ldg(&g_ssrc[i+3]);
        float a0=lrelu(__ldg(&g_asrc2[s0])+adst+__ldg(&g_sae2[i+0]));
        float a1=lrelu(__ldg(&g_asrc2[s1])+adst+__ldg(&g_sae2[i+1]));
        float a2=lrelu(__ldg(&g_asrc2[s2])+adst+__ldg(&g_sae2[i+2]));
        float a3=lrelu(__ldg(&g_asrc2[s3])+adst+__ldg(&g_sae2[i+3]));
        uint2 v0=__ldg((const uint2*)&g_h2[(size_t)s0*64+sl*4]);
        uint2 v1=__ldg((const uint2*)&g_h2[(size_t)s1*64+sl*4]);
        uint2 v2=__ldg((const uint2*)&g_h2[(size_t)s2*64+sl*4]);
        uint2 v3=__ldg((const uint2*)&g_h2[(size_t)s3*64+sl*4]);
        COMB4(a0,v0); COMB4(a1,v1); COMB4(a2,v2); COMB4(a3,v3);
    }
    for(; i<end; i++){
        int s = __ldg(&g_ssrc[i]);
        float a = lrelu(__ldg(&g_asrc2[s])+adst+__ldg(&g_sae2[i]));
        uint2 hv = __ldg((const uint2*)&g_h2[(size_t)s*64+sl*4]);
        COMB4(a,hv);
    }
    float inv = 1.f/sden;
    int g = __ldg(&batch[d]);
    atomicAdd((float4*)&g_pool[g*64 + sl*4],
              make_float4(acc[0]*inv, acc[1]*inv, acc[2]*inv, acc[3]*inv));
    if(sl==0) atomicAdd(&g_cnt[g], 1);
}

// ---------------- 9. final ----------------
__global__ void k_final(float* __restrict__ out, const float* __restrict__ b2){
    int i = blockIdx.x*blockDim.x + threadIdx.x;
    if(i >= Gg*64) return;
    out[i] = g_pool[i] / fmaxf((float)g_cnt[i >> 6], 1.0f) + __ldg(&b2[i & 63]);
}

// ---------------- host launcher ----------------
extern "C" void kernel_launch(void* const* d_in, const int* in_sizes, int n_in,
                              void* d_out, int out_size){
    (void)in_sizes; (void)n_in; (void)out_size;
    const float* x     = (const float*)d_in[0];
    const int*   ei    = (const int*)d_in[1];
    const float* ea    = (const float*)d_in[2];
    const int*   batch = (const int*)d_in[3];
    const float* W1    = (const float*)d_in[4];
    const float* as1   = (const float*)d_in[5];
    const float* ad1   = (const float*)d_in[6];
    const float* We1   = (const float*)d_in[7];
    const float* ae1   = (const float*)d_in[8];
    const float* b1    = (const float*)d_in[9];
    const float* W2    = (const float*)d_in[10];
    const float* as2   = (const float*)d_in[11];
    const float* ad2   = (const float*)d_in[12];
    const float* We2   = (const float*)d_in[13];
    const float* ae2   = (const float*)d_in[14];
    const float* b2    = (const float*)d_in[15];
    float*       out   = (float*)d_out;

    void *p_h1,*p_out1,*p_h2,*p_asrc1,*p_adst1,*p_asrc2,*p_adst2;
    cudaGetSymbolAddress(&p_h1,   g_h1);
    cudaGetSymbolAddress(&p_out1, g_out1);
    cudaGetSymbolAddress(&p_h2,   g_h2);
    cudaGetSymbolAddress(&p_asrc1, g_asrc1);
    cudaGetSymbolAddress(&p_adst1, g_adst1);
    cudaGetSymbolAddress(&p_asrc2, g_asrc2);
    cudaGetSymbolAddress(&p_adst2, g_adst2);

    cudaStream_t s2;
    cudaEvent_t evFork, evJoin;
    cudaStreamCreateWithFlags(&s2, cudaStreamNonBlocking);
    cudaEventCreateWithFlags(&evFork, cudaEventDisableTiming);
    cudaEventCreateWithFlags(&evJoin, cudaEventDisableTiming);

    cudaEventRecord(evFork, 0);

    k_init<<<(Nn+255)/256, 256>>>(We1, ae1, We2, ae2);   // #1
    k_hist<<<(Ee+255)/256, 256>>>(ei);                   // #2
    k_scanA<<<NBLK, 256>>>();                            // #3

    cudaStreamWaitEvent(s2, evFork, 0);
    k_gemm<128,false,float><<<(Nn+63)/64, 128, 0, s2>>>(x, W1, nullptr, as1, ad1,
                        (__half*)p_h1, (float*)p_asrc1, (float*)p_adst1, Nn);  // #4 (ncu target)
    cudaEventRecord(evJoin, s2);

    k_scanB<<<1, 32>>>();                                // #5
    k_scanC<<<NBLK, 256>>>();                            // #6
    k_scatter<<<(Ee+255)/256, 256>>>(ei, ea);            // #7
    k_selfloop<<<(Nn+255)/256, 256>>>();                 // #8

    cudaStreamWaitEvent(0, evJoin, 0);
    k_layer1<<<(Nn/2*32+255)/256, 256>>>();              // #9

    k_gemm<64,true,__half><<<(Nn+63)/64, 128>>>((const __half*)p_out1, W2, b1, as2, ad2,
                        (__half*)p_h2, (float*)p_asrc2, (float*)p_adst2, Nn);  // #10
    k_layer2<<<(Nn/2*32+255)/256, 256>>>(batch);         // #11

    k_final<<<(Gg*64+255)/256, 256>>>(out, b2);          // #12
}